// round 2
// baseline (speedup 1.0000x reference)
#include <cuda_runtime.h>

#define NB 8192      // batch
#define NK 32        // clusters
#define ND 128       // latent dim
#define NORD 8       // AR order
#define NT 24        // output length
#define NE 16        // exogenous dim
#define NIN 96       // input length
#define TB 16        // batch rows per block
#define THREADS 128  // 8 threads per b, each owns 4 clusters

// Scratch (no cudaMalloc allowed): diag(Sinv)^2 per (k,d), plus a flag that
// Sinv has any nonzero off-diagonal (forces the general quadratic-form path).
__device__ float g_diag2[NK * ND];
__device__ int   g_general;

__global__ void zero_flag_kernel() { g_general = 0; }

// Scan sigma_inv: extract squared diagonal, detect off-diagonal content.
__global__ void prep_kernel(const float* __restrict__ sinv) {
    int idx = blockIdx.x * blockDim.x + threadIdx.x;
    if (idx >= NK * ND * ND) return;
    int k = idx / (ND * ND);
    int r = idx - k * (ND * ND);
    int d = r / ND;
    int f = r - d * ND;
    float v = sinv[idx];
    if (d == f) {
        g_diag2[k * ND + d] = v * v;
    } else if (v != 0.0f) {
        g_general = 1;  // benign race: all writers store 1
    }
}

__global__ __launch_bounds__(THREADS)
void fused_kernel(const float* __restrict__ y,
                  const float* __restrict__ z,
                  const float* __restrict__ u,
                  const float* __restrict__ mu,
                  const float* __restrict__ sinv,
                  const float* __restrict__ A,
                  const float* __restrict__ Bx,
                  const float* __restrict__ bias,
                  float* __restrict__ out)
{
    // +1 padding => stride 129 floats => bank = (k + d) mod 32: the 8 distinct
    // k (step 4) and 4 distinct b rows per warp land in distinct banks.
    __shared__ float z_s[TB][ND + 1];
    __shared__ float mu_s[NK][ND + 1];
    __shared__ float dg_s[NK][ND + 1];
    __shared__ float u_s[TB][NE];
    __shared__ float A_s[NK][NORD];
    __shared__ float Bx_s[NK][NE];
    __shared__ float bias_s[NK];
    __shared__ float yh_s[TB][NORD];

    const int t  = threadIdx.x;
    const int b0 = blockIdx.x * TB;

    // ---- cooperative staging ----
    for (int i = t; i < TB * ND; i += THREADS) {
        int bl = i >> 7, d = i & 127;
        z_s[bl][d] = z[(b0 + bl) * ND + d];
    }
    for (int i = t; i < NK * ND; i += THREADS) {
        int k = i >> 7, d = i & 127;
        mu_s[k][d] = mu[i];
        dg_s[k][d] = g_diag2[i];
    }
    for (int i = t; i < TB * NE; i += THREADS) {
        int bl = i / NE, e = i % NE;
        u_s[bl][e] = u[(b0 + bl) * NE + e];
    }
    for (int i = t; i < NK * NORD; i += THREADS) A_s[i / NORD][i % NORD] = A[i];
    for (int i = t; i < NK * NE; i += THREADS)   Bx_s[i / NE][i % NE]   = Bx[i];
    if (t < NK) bias_s[t] = bias[t];
    for (int i = t; i < TB * NORD; i += THREADS) {
        int bl = i >> 3, o = i & 7;
        yh_s[bl][o] = y[(b0 + bl) * NIN + (NIN - NORD) + o];
    }
    __syncthreads();

    const int bl = t >> 3;   // 0..15 : local batch row
    const int kg = t & 7;    // 0..7  : cluster group (4 clusters each)
    const int b  = b0 + bl;

    // ---- squared Mahalanobis distance ----
    float d2[4] = {0.f, 0.f, 0.f, 0.f};
    if (g_general == 0) {
        // diagonal Sinv fast path: d2 = sum_d diag2 * (z - mu)^2
        #pragma unroll 4
        for (int d = 0; d < ND; d++) {
            float zd = z_s[bl][d];
            #pragma unroll
            for (int j = 0; j < 4; j++) {
                int k = kg * 4 + j;
                float g = zd - mu_s[k][d];
                d2[j] = fmaf(dg_s[k][d], g * g, d2[j]);
            }
        }
    } else {
        // general path: d2 = || Sinv^T (mu - z) ||^2   (== d^T Sinv Sinv^T d)
        #pragma unroll
        for (int j = 0; j < 4; j++) {
            int k = kg * 4 + j;
            float acc = 0.f;
            for (int e = 0; e < ND; e++) {
                float v = 0.f;
                for (int d = 0; d < ND; d++) {
                    float gd = mu_s[k][d] - z_s[bl][d];
                    v = fmaf(sinv[(k * ND + d) * ND + e], gd, v);
                }
                acc = fmaf(v, v, acc);
            }
            d2[j] = acc;
        }
    }
    #pragma unroll
    for (int j = 0; j < 4; j++) d2[j] = fmaxf(d2[j], 0.0f);  // MIN_CLAMP

    // ---- softmax(-d2) over K, segmented across the 8 lanes of this b ----
    float m = fmaxf(fmaxf(-d2[0], -d2[1]), fmaxf(-d2[2], -d2[3]));
    #pragma unroll
    for (int s = 1; s < 8; s <<= 1)
        m = fmaxf(m, __shfl_xor_sync(0xffffffffu, m, s));
    float w[4];
    float ssum = 0.f;
    #pragma unroll
    for (int j = 0; j < 4; j++) { w[j] = expf(-d2[j] - m); ssum += w[j]; }
    #pragma unroll
    for (int s = 1; s < 8; s <<= 1)
        ssum += __shfl_xor_sync(0xffffffffu, ssum, s);
    float inv = 1.0f / ssum;
    #pragma unroll
    for (int j = 0; j < 4; j++) w[j] *= inv;   // psi for this thread's clusters

    // ---- exogenous drive ----
    float ex[4];
    #pragma unroll
    for (int j = 0; j < 4; j++) {
        int k = kg * 4 + j;
        float a = bias_s[k];
        #pragma unroll
        for (int e = 0; e < NE; e++) a = fmaf(u_s[bl][e], Bx_s[k][e], a);
        ex[j] = a;
    }

    // ---- AR recurrence (history in registers) + psi-weighted combine ----
    float hist[4][NORD];
    #pragma unroll
    for (int j = 0; j < 4; j++)
        #pragma unroll
        for (int o = 0; o < NORD; o++) hist[j][o] = yh_s[bl][o];

    float part[NT];
    #pragma unroll
    for (int step = 0; step < NT; step++) {
        float acc = 0.f;
        #pragma unroll
        for (int j = 0; j < 4; j++) {
            int k = kg * 4 + j;
            float nxt = ex[j];
            #pragma unroll
            for (int o = 0; o < NORD; o++) nxt = fmaf(hist[j][o], A_s[k][o], nxt);
            #pragma unroll
            for (int o = 0; o < NORD - 1; o++) hist[j][o] = hist[j][o + 1];
            hist[j][NORD - 1] = nxt;
            acc = fmaf(w[j], nxt, acc);
        }
        part[step] = acc;
    }

    // reduce the 8 partial mixtures per b
    #pragma unroll
    for (int s = 1; s < 8; s <<= 1) {
        #pragma unroll
        for (int step = 0; step < NT; step++)
            part[step] += __shfl_xor_sync(0xffffffffu, part[step], s);
    }

    if (kg == 0) {
        // out row is 24 floats starting at b*24*4 bytes (96B, 16B aligned)
        float4* o4 = reinterpret_cast<float4*>(out + b * NT);
        #pragma unroll
        for (int q = 0; q < NT / 4; q++) {
            o4[q] = make_float4(part[q * 4 + 0], part[q * 4 + 1],
                                part[q * 4 + 2], part[q * 4 + 3]);
        }
    }
}

// x_recon region (and anything beyond y_con) must be zeroed: d_out is poisoned.
__global__ void zero_tail_kernel(float* __restrict__ out, int n0, int n) {
    int i = n0 + blockIdx.x * blockDim.x + threadIdx.x;
    if (i < n) out[i] = 0.0f;
}

extern "C" void kernel_launch(void* const* d_in, const int* in_sizes, int n_in,
                              void* d_out, int out_size) {
    const float* y    = (const float*)d_in[0];
    const float* z    = (const float*)d_in[1];
    const float* u    = (const float*)d_in[2];
    const float* mu   = (const float*)d_in[3];
    const float* sinv = (const float*)d_in[4];
    const float* A    = (const float*)d_in[5];
    const float* Bx   = (const float*)d_in[6];
    const float* bias = (const float*)d_in[7];
    float* out = (float*)d_out;

    zero_flag_kernel<<<1, 1>>>();
    prep_kernel<<<(NK * ND * ND + 255) / 256, 256>>>(sinv);
    fused_kernel<<<NB / TB, THREADS>>>(y, z, u, mu, sinv, A, Bx, bias, out);

    int n0 = NB * NT;
    int tail = out_size - n0;
    if (tail > 0)
        zero_tail_kernel<<<(tail + 255) / 256, 256>>>(out, n0, out_size);
}

// round 5
// speedup vs baseline: 1.4184x; 1.4184x over previous
#include <cuda_runtime.h>

#define NB 8192      // batch
#define NK 32        // clusters
#define ND 128       // latent dim
#define NORD 8       // AR order
#define NT 24        // output length
#define NE 16        // exogenous dim
#define NIN 96       // input length
#define TB 16        // batch rows per block
#define THREADS 128  // 8 threads per b, each owns 4 clusters (2 packed pairs)

typedef unsigned long long ull;

// ---- packed fp32x2 helpers (FFMA2 only reachable via PTX) ----
__device__ __forceinline__ ull pk2(float lo, float hi) {
    ull r; asm("mov.b64 %0,{%1,%2};" : "=l"(r) : "f"(lo), "f"(hi)); return r;
}
__device__ __forceinline__ void upk2(ull v, float& lo, float& hi) {
    asm("mov.b64 {%0,%1},%2;" : "=f"(lo), "=f"(hi) : "l"(v));
}
__device__ __forceinline__ ull fma2(ull a, ull b, ull c) {
    ull d; asm("fma.rn.f32x2 %0,%1,%2,%3;" : "=l"(d) : "l"(a), "l"(b), "l"(c)); return d;
}
__device__ __forceinline__ ull add2_(ull a, ull b) {
    ull d; asm("add.rn.f32x2 %0,%1,%2;" : "=l"(d) : "l"(a), "l"(b)); return d;
}
__device__ __forceinline__ ull mul2_(ull a, ull b) {
    ull d; asm("mul.rn.f32x2 %0,%1,%2;" : "=l"(d) : "l"(a), "l"(b)); return d;
}

// Scratch (no cudaMalloc allowed). Flags are 0-init at module load and only
// ever transition 0 -> 1; BOTH states give correct results (1 = slower path),
// so they are never reset per call.
__device__ __align__(16) float g_sdT[ND * NK];   // |diag(Sinv_k)| transposed [d][k]
__device__ __align__(16) float g_nsmu[ND * NK];  // -|diag| * mu, transposed [d][k]
__device__ __align__(16) float g_sd0[ND];        // k=0 diag (uniform fast path)
__device__ int g_general;   // any off-diagonal nonzero -> full quadratic form
__device__ int g_nonuni;    // diag differs across k -> per-k diagonal path

// grid = 4 blocks per k (128 blocks), 128 threads. Coalesced row scans.
__global__ void prep_kernel(const float* __restrict__ sinv,
                            const float* __restrict__ mu) {
    const int k = blockIdx.x >> 2;
    const int q = blockIdx.x & 3;
    const int t = threadIdx.x;
    const float* S = sinv + k * ND * ND;
    int bad = 0;
    #pragma unroll 4
    for (int r0 = 0; r0 < 32; r0++) {
        int r = q * 32 + r0;
        float v = S[r * ND + t];
        if (t == r) {
            float sd = fabsf(v);
            float sd0 = fabsf(sinv[r * ND + r]);  // k = 0 diagonal element
            if (sd != sd0) g_nonuni = 1;          // benign race, 0 -> 1 only
            g_sdT[r * NK + k] = sd;
            g_nsmu[r * NK + k] = -sd * mu[k * ND + r];
            if (k == 0) g_sd0[r] = sd;
        } else if (v != 0.0f) {
            bad = 1;
        }
    }
    if (bad) g_general = 1;  // benign race
}

__global__ __launch_bounds__(THREADS, 4)
void fused_kernel(const float* __restrict__ y,
                  const float* __restrict__ z,
                  const float* __restrict__ u,
                  const float* __restrict__ mu,
                  const float* __restrict__ sinv,
                  const float* __restrict__ A,
                  const float* __restrict__ Bx,
                  const float* __restrict__ bias,
                  float* __restrict__ out)
{
    __shared__ __align__(16) float z_t[ND][TB + 1];   // [d][bl], pad -> conflict-free
    __shared__ __align__(16) float nsmu_t[ND][NK];    // [d][k] rows are 128B
    __shared__ __align__(16) float sd0_s[ND];
    __shared__ __align__(16) float u_s[TB][NE];
    __shared__ __align__(16) float A_t[NORD][NK];     // [o][k]
    __shared__ __align__(16) float Bx_t[NE][NK];      // [e][k]
    __shared__ __align__(16) float bias_s[NK];
    __shared__ __align__(16) float yh_s[TB][NORD];
    __shared__ __align__(16) float part_s[TB][NT];

    const int t  = threadIdx.x;
    const int b0 = blockIdx.x * TB;

    // ---- zero this block's x_recon slice (overlaps with staging) ----
    {
        float4 z4 = make_float4(0.f, 0.f, 0.f, 0.f);
        float4* xr = reinterpret_cast<float4*>(out + NB * NT + b0 * NIN);
        #pragma unroll
        for (int j = 0; j < (TB * NIN / 4) / THREADS; j++)  // 3 iters
            xr[j * THREADS + t] = z4;
    }

    // ---- cooperative staging ----
    #pragma unroll
    for (int i = t; i < TB * ND; i += THREADS) {
        int bl = i >> 7, d = i & 127;
        z_t[d][bl] = z[(b0 + bl) * ND + d];
    }
    {   // nsmu: straight float4 copy (already transposed by prep)
        const float4* src = reinterpret_cast<const float4*>(g_nsmu);
        float4* dst = reinterpret_cast<float4*>(&nsmu_t[0][0]);
        #pragma unroll
        for (int i = t; i < ND * NK / 4; i += THREADS) dst[i] = src[i];
    }
    if (t < ND) sd0_s[t] = g_sd0[t];
    #pragma unroll
    for (int i = t; i < TB * NE; i += THREADS)
        u_s[i >> 4][i & 15] = u[(b0 + (i >> 4)) * NE + (i & 15)];
    // A is NK*NORD = 256 elements > THREADS: MUST be a grid-stride loop
    #pragma unroll
    for (int i = t; i < NK * NORD; i += THREADS) A_t[i & 7][i >> 3] = A[i];
    #pragma unroll
    for (int i = t; i < NK * NE; i += THREADS) Bx_t[i & 15][i >> 4] = Bx[i];
    if (t < NK) bias_s[t] = bias[t];
    if (t < TB * NORD)
        yh_s[t >> 3][t & 7] = y[(b0 + (t >> 3)) * NIN + (NIN - NORD) + (t & 7)];
    __syncthreads();

    const int bl = t >> 3;   // local batch row
    const int kg = t & 7;    // cluster group: clusters kg*4 .. kg*4+3
    const int kb = kg * 4;

    // ---- squared Mahalanobis distance, packed over cluster pairs ----
    ull acc0 = 0ULL, acc1 = 0ULL;   // packed +0.0f pairs
    if (g_general == 0) {
        if (g_nonuni == 0) {
            // diag uniform across k: t_k = sd0*z - sd0*mu_k
            #pragma unroll 8
            for (int d = 0; d < ND; d++) {
                float zd  = z_t[d][bl];
                float szd = sd0_s[d] * zd;
                ull  szd2 = pk2(szd, szd);
                ulonglong2 nv = *reinterpret_cast<const ulonglong2*>(&nsmu_t[d][kb]);
                ull t0 = add2_(szd2, nv.x);
                ull t1 = add2_(szd2, nv.y);
                acc0 = fma2(t0, t0, acc0);
                acc1 = fma2(t1, t1, acc1);
            }
        } else {
            // per-k diagonal: t_k = sd_k*z - sd_k*mu_k  (sd from gmem/L1)
            #pragma unroll 4
            for (int d = 0; d < ND; d++) {
                float zd = z_t[d][bl];
                ull zz = pk2(zd, zd);
                ulonglong2 sv = *reinterpret_cast<const ulonglong2*>(&g_sdT[d * NK + kb]);
                ulonglong2 nv = *reinterpret_cast<const ulonglong2*>(&nsmu_t[d][kb]);
                ull t0 = fma2(sv.x, zz, nv.x);
                ull t1 = fma2(sv.y, zz, nv.y);
                acc0 = fma2(t0, t0, acc0);
                acc1 = fma2(t1, t1, acc1);
            }
        }
    }

    float d2[4];
    upk2(acc0, d2[0], d2[1]);
    upk2(acc1, d2[2], d2[3]);
    if (g_general != 0) {
        // full quadratic form fallback: d2 = || Sinv^T (mu - z) ||^2
        #pragma unroll
        for (int j = 0; j < 4; j++) {
            int k = kb + j;
            float acc = 0.f;
            for (int e = 0; e < ND; e++) {
                float v = 0.f;
                for (int d = 0; d < ND; d++) {
                    float gd = mu[k * ND + d] - z_t[d][bl];
                    v = fmaf(sinv[(k * ND + d) * ND + e], gd, v);
                }
                acc = fmaf(v, v, acc);
            }
            d2[j] = acc;
        }
    }
    #pragma unroll
    for (int j = 0; j < 4; j++) d2[j] = fmaxf(d2[j], 0.0f);  // MIN_CLAMP

    // ---- softmax(-d2) over K, segmented across the 8 lanes of this b ----
    float m = fmaxf(fmaxf(-d2[0], -d2[1]), fmaxf(-d2[2], -d2[3]));
    #pragma unroll
    for (int s = 1; s < 8; s <<= 1)
        m = fmaxf(m, __shfl_xor_sync(0xffffffffu, m, s));
    float w[4];
    float ssum = 0.f;
    #pragma unroll
    for (int j = 0; j < 4; j++) { w[j] = expf(-d2[j] - m); ssum += w[j]; }
    #pragma unroll
    for (int s = 1; s < 8; s <<= 1)
        ssum += __shfl_xor_sync(0xffffffffu, ssum, s);
    float inv = 1.0f / ssum;
    ull w2_0 = pk2(w[0] * inv, w[1] * inv);
    ull w2_1 = pk2(w[2] * inv, w[3] * inv);

    // ---- exogenous drive (packed) ----
    ulonglong2 bq = *reinterpret_cast<const ulonglong2*>(&bias_s[kb]);
    ull ex0 = bq.x, ex1 = bq.y;
    #pragma unroll
    for (int e = 0; e < NE; e++) {
        float ue = u_s[bl][e];
        ull uu = pk2(ue, ue);
        ulonglong2 bx = *reinterpret_cast<const ulonglong2*>(&Bx_t[e][kb]);
        ex0 = fma2(uu, bx.x, ex0);
        ex1 = fma2(uu, bx.y, ex1);
    }

    // ---- AR recurrence: packed pairs, circular history (no shift movs) ----
    ull a0[NORD], a1[NORD];
    #pragma unroll
    for (int o = 0; o < NORD; o++) {
        ulonglong2 av = *reinterpret_cast<const ulonglong2*>(&A_t[o][kb]);
        a0[o] = av.x; a1[o] = av.y;
    }
    ull h0[NORD], h1[NORD];
    #pragma unroll
    for (int o = 0; o < NORD; o++) {
        float yv = yh_s[bl][o];
        ull yp = pk2(yv, yv);
        h0[o] = yp; h1[o] = yp;
    }

    #pragma unroll
    for (int s = 0; s < NT; s++) {
        ull n0 = ex0, n1 = ex1;
        #pragma unroll
        for (int o = 0; o < NORD; o++) {
            n0 = fma2(h0[(s + o) & 7], a0[o], n0);
            n1 = fma2(h1[(s + o) & 7], a1[o], n1);
        }
        h0[s & 7] = n0;
        h1[s & 7] = n1;
        ull c = fma2(w2_0, n0, mul2_(w2_1, n1));
        float ca, cb; upk2(c, ca, cb);
        float part = ca + cb;
        part += __shfl_xor_sync(0xffffffffu, part, 1);
        part += __shfl_xor_sync(0xffffffffu, part, 2);
        part += __shfl_xor_sync(0xffffffffu, part, 4);
        if (kg == 0) part_s[bl][s] = part;
    }
    __syncthreads();

    // ---- coalesced float4 output store ----
    if (t < TB * NT / 4) {             // 96 threads
        int row = t / (NT / 4);        // /6
        int q   = t % (NT / 4);
        float4 v = make_float4(part_s[row][q * 4 + 0], part_s[row][q * 4 + 1],
                               part_s[row][q * 4 + 2], part_s[row][q * 4 + 3]);
        *reinterpret_cast<float4*>(out + (b0 + row) * NT + q * 4) = v;
    }
}

// Safety net: only used if out_size exceeds the expected layout.
__global__ void zero_extra_kernel(float* __restrict__ out, int n0, int n) {
    int i = n0 + blockIdx.x * blockDim.x + threadIdx.x;
    if (i < n) out[i] = 0.0f;
}

extern "C" void kernel_launch(void* const* d_in, const int* in_sizes, int n_in,
                              void* d_out, int out_size) {
    const float* y    = (const float*)d_in[0];
    const float* z    = (const float*)d_in[1];
    const float* u    = (const float*)d_in[2];
    const float* mu   = (const float*)d_in[3];
    const float* sinv = (const float*)d_in[4];
    const float* A    = (const float*)d_in[5];
    const float* Bx   = (const float*)d_in[6];
    const float* bias = (const float*)d_in[7];
    float* out = (float*)d_out;

    prep_kernel<<<NK * 4, THREADS>>>(sinv, mu);
    fused_kernel<<<NB / TB, THREADS>>>(y, z, u, mu, sinv, A, Bx, bias, out);

    int n0 = NB * (NT + NIN);  // fused zeroes [NB*NT, NB*(NT+NIN))
    if (out_size > n0) {
        int extra = out_size - n0;
        zero_extra_kernel<<<(extra + 255) / 256, 256>>>(out, n0, out_size);
    }
}

// round 7
// speedup vs baseline: 1.5317x; 1.0799x over previous
#include <cuda_runtime.h>

#define NB 8192      // batch
#define NK 32        // clusters
#define ND 128       // latent dim
#define NORD 8       // AR order
#define NT 24        // output length
#define NE 16        // exogenous dim
#define NIN 96       // input length
#define TB 8         // batch rows per block
#define THREADS 128  // 16 lanes per b, each owns 2 clusters (1 packed pair)

typedef unsigned long long ull;

// ---- packed fp32x2 helpers (each lane is IEEE fp32; FFMA2 via PTX only) ----
__device__ __forceinline__ ull pk2(float lo, float hi) {
    ull r; asm("mov.b64 %0,{%1,%2};" : "=l"(r) : "f"(lo), "f"(hi)); return r;
}
__device__ __forceinline__ void upk2(ull v, float& lo, float& hi) {
    asm("mov.b64 {%0,%1},%2;" : "=f"(lo), "=f"(hi) : "l"(v));
}
__device__ __forceinline__ ull fma2(ull a, ull b, ull c) {
    ull d; asm("fma.rn.f32x2 %0,%1,%2,%3;" : "=l"(d) : "l"(a), "l"(b), "l"(c)); return d;
}
__device__ __forceinline__ ull add2_(ull a, ull b) {
    ull d; asm("add.rn.f32x2 %0,%1,%2;" : "=l"(d) : "l"(a), "l"(b)); return d;
}
__device__ __forceinline__ ull mul2_(ull a, ull b) {
    ull d; asm("mul.rn.f32x2 %0,%1,%2;" : "=l"(d) : "l"(a), "l"(b)); return d;
}

// Scratch (no cudaMalloc). Flags are 0-init at module load and only ever go
// 0 -> 1; BOTH states give correct results (1 = slower path). Never reset.
__device__ __align__(16) float g_dgT [ND * NK];   // diag(Sinv_k)^2, [d][k]
__device__ __align__(16) float g_nmuT[ND * NK];   // -mu, [d][k]
__device__ __align__(16) float g_dg0 [ND];        // k=0 diag^2 (uniform path)
__device__ int g_general;   // any off-diagonal nonzero -> full quadratic form
__device__ int g_nonuni;    // diag differs across k -> per-k dg path

// grid = 8 blocks per k (256 blocks), 128 threads, 16 rows per block.
__global__ void prep_kernel(const float* __restrict__ sinv,
                            const float* __restrict__ mu) {
    const int k = blockIdx.x >> 3;
    const int o = blockIdx.x & 7;
    const int t = threadIdx.x;
    const float* S = sinv + k * ND * ND;
    int bad = 0;
    #pragma unroll 8
    for (int r0 = 0; r0 < 16; r0++) {
        int r = o * 16 + r0;
        float v = S[r * ND + t];
        if (t == r) {
            float sd0 = sinv[r * ND + r];          // k = 0 diagonal
            if (fabsf(v) != fabsf(sd0)) g_nonuni = 1;  // benign race, 0 -> 1
            g_dgT [r * NK + k] = v * v;
            g_nmuT[r * NK + k] = -mu[k * ND + r];
            if (k == 0) g_dg0[r] = v * v;
        } else if (v != 0.0f) {
            bad = 1;
        }
    }
    if (bad) g_general = 1;  // benign race
}

__global__ __launch_bounds__(THREADS, 8)
void fused_kernel(const float* __restrict__ y,
                  const float* __restrict__ z,
                  const float* __restrict__ u,
                  const float* __restrict__ mu,
                  const float* __restrict__ sinv,
                  const float* __restrict__ A,
                  const float* __restrict__ Bx,
                  const float* __restrict__ bias,
                  float* __restrict__ out)
{
    __shared__ __align__(16) float zs_t[TB][ND + 4];  // raw z rows (pad 4: 528B stride, 16B aligned)
    __shared__ __align__(16) float nmu_t[ND][NK];     // -mu, [d][k]: rows are 128B
    __shared__ __align__(16) float dg0_s[ND];         // uniform diag^2
    __shared__ __align__(16) float u_s[TB][NE];
    __shared__ __align__(16) float A_t[NORD][NK];     // [o][k]
    __shared__ __align__(16) float Bx_t[NE][NK];      // [e][k]
    __shared__ __align__(16) float bias_s[NK];
    __shared__ __align__(16) float yh_s[TB][NORD];
    __shared__ __align__(16) float part_s[TB][NT];

    const int t  = threadIdx.x;
    const int b0 = blockIdx.x * TB;
    const int gen  = g_general;
    const int nonu = g_nonuni;

    // ---- zero this block's x_recon slice (overlaps with staging) ----
    {
        float4 z4 = make_float4(0.f, 0.f, 0.f, 0.f);
        float4* xr = reinterpret_cast<float4*>(out + NB * NT + b0 * NIN);
        xr[t] = z4;                                  // 128 of 192
        if (t < TB * NIN / 4 - THREADS) xr[THREADS + t] = z4;  // remaining 64
    }

    // ---- cooperative staging ----
    #pragma unroll
    for (int j = 0; j < TB * ND / THREADS; j++) {    // 8 iters
        int i = j * THREADS + t;
        int bl = i >> 7, d = i & 127;
        zs_t[bl][d] = z[(b0 + bl) * ND + d];
    }
    {   // -mu: straight float4 copy (already [d][k] from prep)
        const float4* src = reinterpret_cast<const float4*>(g_nmuT);
        float4* dst = reinterpret_cast<float4*>(&nmu_t[0][0]);
        #pragma unroll
        for (int j = 0; j < ND * NK / 4 / THREADS; j++)  // 8 iters
            dst[j * THREADS + t] = src[j * THREADS + t];
    }
    if (t < ND) dg0_s[t] = g_dg0[t];
    u_s[t >> 4][t & 15] = u[(b0 + (t >> 4)) * NE + (t & 15)];
    #pragma unroll
    for (int i = t; i < NK * NORD; i += THREADS) A_t[i & 7][i >> 3] = A[i];
    #pragma unroll
    for (int i = t; i < NK * NE; i += THREADS) Bx_t[i & 15][i >> 4] = Bx[i];
    if (t < NK) bias_s[t] = bias[t];
    if (t < TB * NORD)
        yh_s[t >> 3][t & 7] = y[(b0 + (t >> 3)) * NIN + (NIN - NORD) + (t & 7)];
    __syncthreads();

    const int bl = t >> 4;   // local batch row (0..7)
    const int kg = t & 15;   // lane within b: clusters kg*2, kg*2+1
    const int kb = kg * 2;

    // ---- squared Mahalanobis distance, R2 factoring (matches reference):
    //      g = z - mu ; gg = g*g ; d2 += diag^2 * gg ----
    float d20, d21;
    if (gen == 0) {
        ull acc = 0ULL;  // packed +0.0f pair
        if (nonu == 0) {
            // uniform diag across k: dg scalar per d from smem
            #pragma unroll
            for (int d = 0; d < ND; d += 4) {
                float4 zq  = *reinterpret_cast<const float4*>(&zs_t[bl][d]);
                float4 dgq = *reinterpret_cast<const float4*>(&dg0_s[d]);
                #pragma unroll
                for (int j = 0; j < 4; j++) {
                    float zd = (j == 0) ? zq.x : (j == 1) ? zq.y : (j == 2) ? zq.z : zq.w;
                    float dg = (j == 0) ? dgq.x : (j == 1) ? dgq.y : (j == 2) ? dgq.z : dgq.w;
                    ull nm = *reinterpret_cast<const ull*>(&nmu_t[d + j][kb]);
                    ull g  = add2_(pk2(zd, zd), nm);
                    ull gg = mul2_(g, g);
                    acc = fma2(pk2(dg, dg), gg, acc);
                }
            }
        } else {
            // per-k diag: dg pairs from gmem table (L1-resident, 16KB)
            #pragma unroll 4
            for (int d = 0; d < ND; d++) {
                float zd = zs_t[bl][d];
                ull nm  = *reinterpret_cast<const ull*>(&nmu_t[d][kb]);
                ull dgp = *reinterpret_cast<const ull*>(&g_dgT[d * NK + kb]);
                ull g  = add2_(pk2(zd, zd), nm);
                ull gg = mul2_(g, g);
                acc = fma2(dgp, gg, acc);
            }
        }
        upk2(acc, d20, d21);
    } else {
        // full quadratic form fallback: d2 = || Sinv^T (mu - z) ||^2
        float d2v[2];
        #pragma unroll
        for (int j = 0; j < 2; j++) {
            int k = kb + j;
            float acc = 0.f;
            for (int e = 0; e < ND; e++) {
                float v = 0.f;
                for (int d = 0; d < ND; d++) {
                    float gd = mu[k * ND + d] - zs_t[bl][d];
                    v = fmaf(sinv[(k * ND + d) * ND + e], gd, v);
                }
                acc = fmaf(v, v, acc);
            }
            d2v[j] = acc;
        }
        d20 = d2v[0]; d21 = d2v[1];
    }
    d20 = fmaxf(d20, 0.0f);   // MIN_CLAMP
    d21 = fmaxf(d21, 0.0f);

    // ---- softmax(-d2) over K, segmented across the 16 lanes of this b ----
    float m = fmaxf(-d20, -d21);
    #pragma unroll
    for (int s = 1; s < 16; s <<= 1)
        m = fmaxf(m, __shfl_xor_sync(0xffffffffu, m, s));
    float w0 = expf(-d20 - m), w1 = expf(-d21 - m);
    float ssum = w0 + w1;
    #pragma unroll
    for (int s = 1; s < 16; s <<= 1)
        ssum += __shfl_xor_sync(0xffffffffu, ssum, s);
    float inv = 1.0f / ssum;
    ull w2 = pk2(w0 * inv, w1 * inv);

    // ---- exogenous drive ----
    float e0 = bias_s[kb], e1 = bias_s[kb + 1];
    #pragma unroll
    for (int e = 0; e < NE; e++) {
        float ue = u_s[bl][e];
        float2 bx = *reinterpret_cast<const float2*>(&Bx_t[e][kb]);
        e0 = fmaf(ue, bx.x, e0);
        e1 = fmaf(ue, bx.y, e1);
    }
    ull ex2 = pk2(e0, e1);

    // ---- AR recurrence: packed pair, circular history (compile-time idx) ----
    ull a[NORD], h[NORD];
    #pragma unroll
    for (int o = 0; o < NORD; o++) {
        float2 av = *reinterpret_cast<const float2*>(&A_t[o][kb]);
        a[o] = pk2(av.x, av.y);
        float yv = yh_s[bl][o];
        h[o] = pk2(yv, yv);
    }

    #pragma unroll
    for (int s = 0; s < NT; s++) {
        ull n = ex2;
        #pragma unroll
        for (int o = 0; o < NORD; o++)
            n = fma2(h[(s + o) & 7], a[o], n);
        h[s & 7] = n;
        ull c = mul2_(w2, n);
        float ca, cb; upk2(c, ca, cb);
        float part = ca + cb;
        part += __shfl_xor_sync(0xffffffffu, part, 1);
        part += __shfl_xor_sync(0xffffffffu, part, 2);
        part += __shfl_xor_sync(0xffffffffu, part, 4);
        part += __shfl_xor_sync(0xffffffffu, part, 8);
        if (kg == 0) part_s[bl][s] = part;
    }
    __syncthreads();

    // ---- coalesced float4 output store ----
    if (t < TB * NT / 4) {             // 48 threads
        int row = t / (NT / 4);
        int q   = t % (NT / 4);
        float4 v = make_float4(part_s[row][q * 4 + 0], part_s[row][q * 4 + 1],
                               part_s[row][q * 4 + 2], part_s[row][q * 4 + 3]);
        *reinterpret_cast<float4*>(out + (b0 + row) * NT + q * 4) = v;
    }
}

// Safety net: only used if out_size exceeds the expected layout.
__global__ void zero_extra_kernel(float* __restrict__ out, int n0, int n) {
    int i = n0 + blockIdx.x * blockDim.x + threadIdx.x;
    if (i < n) out[i] = 0.0f;
}

extern "C" void kernel_launch(void* const* d_in, const int* in_sizes, int n_in,
                              void* d_out, int out_size) {
    const float* y    = (const float*)d_in[0];
    const float* z    = (const float*)d_in[1];
    const float* u    = (const float*)d_in[2];
    const float* mu   = (const float*)d_in[3];
    const float* sinv = (const float*)d_in[4];
    const float* A    = (const float*)d_in[5];
    const float* Bx   = (const float*)d_in[6];
    const float* bias = (const float*)d_in[7];
    float* out = (float*)d_out;

    prep_kernel<<<NK * 8, THREADS>>>(sinv, mu);
    fused_kernel<<<NB / TB, THREADS>>>(y, z, u, mu, sinv, A, Bx, bias, out);

    int n0 = NB * (NT + NIN);  // fused zeroes [NB*NT, NB*(NT+NIN))
    if (out_size > n0) {
        int extra = out_size - n0;
        zero_extra_kernel<<<(extra + 255) / 256, 256>>>(out, n0, out_size);
    }
}

// round 9
// speedup vs baseline: 1.5487x; 1.0111x over previous
#include <cuda_runtime.h>

#define NB 8192      // batch
#define NK 32        // clusters
#define ND 128       // latent dim
#define NORD 8       // AR order
#define NT 24        // output length
#define NE 16        // exogenous dim
#define NIN 96       // input length
#define TB 8         // batch rows per block
#define THREADS 128  // 16 lanes per b; lane kg owns clusters kg and kg+16

typedef unsigned long long ull;

// ---- packed fp32x2 helpers (each lane is IEEE fp32; f32x2 via PTX only) ----
__device__ __forceinline__ ull pk2(float lo, float hi) {
    ull r; asm("mov.b64 %0,{%1,%2};" : "=l"(r) : "f"(lo), "f"(hi)); return r;
}
__device__ __forceinline__ void upk2(ull v, float& lo, float& hi) {
    asm("mov.b64 {%0,%1},%2;" : "=f"(lo), "=f"(hi) : "l"(v));
}
__device__ __forceinline__ ull fma2(ull a, ull b, ull c) {
    ull d; asm("fma.rn.f32x2 %0,%1,%2,%3;" : "=l"(d) : "l"(a), "l"(b), "l"(c)); return d;
}
__device__ __forceinline__ ull add2_(ull a, ull b) {
    ull d; asm("add.rn.f32x2 %0,%1,%2;" : "=l"(d) : "l"(a), "l"(b)); return d;
}
__device__ __forceinline__ ull mul2_(ull a, ull b) {
    ull d; asm("mul.rn.f32x2 %0,%1,%2;" : "=l"(d) : "l"(a), "l"(b)); return d;
}

// Scratch (no cudaMalloc). Flags are 0-init at module load and only ever go
// 0 -> 1; all flag states give correct results (set = slower path). Data
// tables are rewritten by prep on every call (deterministic).
__device__ __align__(16) ull   g_nmuP[ND * 16];   // (-mu[kg][d], -mu[kg+16][d])
__device__ __align__(16) ull   g_dgP [ND];        // (dg0[d], dg0[d]), dg = diag^2
__device__ __align__(16) float g_dgKD[NK * ND];   // diag^2, [k][d] (per-k path)
__device__ int g_general;    // any off-diagonal nonzero -> full quadratic form
__device__ int g_nonuni;     // diag^2 differs across k  -> per-k path

// grid = 4 blocks per k (128 blocks), 128 threads; float4 scan, MLP=8.
// Blocks 0..15 additionally pack the -mu pair table and dg pair table.
__global__ void prep_kernel(const float* __restrict__ sinv,
                            const float* __restrict__ mu) {
    const int k = blockIdx.x >> 2;
    const int q = blockIdx.x & 3;
    const int t = threadIdx.x;
    const float* S = sinv + k * ND * ND;
    int bad = 0;
    #pragma unroll
    for (int j = 0; j < 8; j++) {
        int i  = j * THREADS + t;       // 0..1023 chunk id within quarter
        int rl = i >> 5, c = i & 31;    // row-local, float4 column
        int row = q * 32 + rl;
        float4 v = *reinterpret_cast<const float4*>(S + row * ND + c * 4);
        int base = c * 4;
        if (base + 0 != row && v.x != 0.0f) bad = 1;
        if (base + 1 != row && v.y != 0.0f) bad = 1;
        if (base + 2 != row && v.z != 0.0f) bad = 1;
        if (base + 3 != row && v.w != 0.0f) bad = 1;
        if (row >= base && row < base + 4) {
            float dv = (row == base) ? v.x : (row == base + 1) ? v.y
                     : (row == base + 2) ? v.z : v.w;
            float dg = dv * dv;
            g_dgKD[k * ND + row] = dg;
            float d0 = sinv[row * ND + row];             // k=0 same-row diag
            if (dg != d0 * d0) g_nonuni = 1;             // benign race 0->1
        }
    }
    if (bad) g_general = 1;                              // benign race 0->1

    // pack tables (first 16 blocks: 16 blocks x 8 d-rows = all 128 d)
    if (blockIdx.x < 16) {
        int d  = blockIdx.x * 8 + (t >> 4);
        int kg = t & 15;
        float mA = mu[kg * ND + d];
        float mB = mu[(kg + 16) * ND + d];
        g_nmuP[d * 16 + kg] = pk2(-mA, -mB);
        if (kg == 0) {
            float dv = sinv[d * ND + d];   // k = 0 diagonal
            g_dgP[d] = pk2(dv * dv, dv * dv);
        }
    }
}

__global__ __launch_bounds__(THREADS, 7)
void fused_kernel(const float* __restrict__ y,
                  const float* __restrict__ z,
                  const float* __restrict__ u,
                  const float* __restrict__ mu,
                  const float* __restrict__ sinv,
                  const float* __restrict__ A,
                  const float* __restrict__ Bx,
                  const float* __restrict__ bias,
                  float* __restrict__ out)
{
    __shared__ __align__(16) ull   zP[TB][ND + 2];     // (z,z) pairs, pad 2
    __shared__ __align__(16) ull   nmuP_s[ND * 16];    // (-muA,-muB), [d][kg]
    __shared__ __align__(16) ull   dgP_s[ND];          // (dg,dg)
    __shared__ __align__(16) float u_s[TB][NE];
    __shared__ __align__(16) float2 A_p[NORD][16];     // (A[kg][o], A[kg+16][o])
    __shared__ __align__(16) float2 Bx_p[NE][16];      // (Bx[kg][e], Bx[kg+16][e])
    __shared__ __align__(16) float2 bias_p[16];
    __shared__ __align__(16) float yh_s[TB][NORD];
    __shared__ __align__(16) float part2[TB][2][28];   // AR partials (2 per b)

    const int t  = threadIdx.x;
    const int b0 = blockIdx.x * TB;
    const int gen  = g_general;
    const int nonu = g_nonuni;

    // ---- zero this block's x_recon slice (overlaps with staging) ----
    {
        float4 z4 = make_float4(0.f, 0.f, 0.f, 0.f);
        float4* xr = reinterpret_cast<float4*>(out + NB * NT + b0 * NIN);
        xr[t] = z4;                                         // 128 of 192
        if (t < TB * NIN / 4 - THREADS) xr[THREADS + t] = z4;  // last 64
    }

    // ---- cooperative staging ----
    #pragma unroll
    for (int j = 0; j < TB * ND / THREADS; j++) {       // 8 iters
        int i = j * THREADS + t;
        int bl = i >> 7, d = i & 127;
        float zv = z[(b0 + bl) * ND + d];
        zP[bl][d] = pk2(zv, zv);
    }
    {   // nmuP: straight ull2 copy (already packed by prep)
        const ulonglong2* src = reinterpret_cast<const ulonglong2*>(g_nmuP);
        ulonglong2* dst = reinterpret_cast<ulonglong2*>(nmuP_s);
        #pragma unroll
        for (int j = 0; j < ND * 16 / 2 / THREADS; j++)  // 8 iters
            dst[j * THREADS + t] = src[j * THREADS + t];
    }
    dgP_s[t] = g_dgP[t];
    u_s[t >> 4][t & 15] = u[(b0 + (t >> 4)) * NE + (t & 15)];
    {   // A pairs: 128 entries
        int o = t >> 4, kg_ = t & 15;
        A_p[o][kg_] = make_float2(A[kg_ * NORD + o], A[(kg_ + 16) * NORD + o]);
    }
    #pragma unroll
    for (int j = 0; j < 2; j++) {   // Bx pairs: 256 entries
        int i = j * THREADS + t;
        int e = i >> 4, kg_ = i & 15;
        Bx_p[e][kg_] = make_float2(Bx[kg_ * NE + e], Bx[(kg_ + 16) * NE + e]);
    }
    if (t < 16) bias_p[t] = make_float2(bias[t], bias[t + 16]);
    if (t < TB * NORD)
        yh_s[t >> 3][t & 7] = y[(b0 + (t >> 3)) * NIN + (NIN - NORD) + (t & 7)];
    __syncthreads();

    const int bl = t >> 4;    // local batch row (0..7)
    const int kg = t & 15;    // lane within b; clusters kg and kg+16

    // ---- squared Mahalanobis distance, R2/R7 op sequence (frozen):
    //      g = z + (-mu); gg = g*g; acc = fma(dg, gg, acc), d sequential ----
    float d2A, d2B;
    const ull* zrow = &zP[bl][0];
    if (gen == 0) {
        ull acc = 0ULL;  // packed +0.0f pair (lanes: cluster kg, kg+16)
        if (nonu == 0) {
            #pragma unroll 8
            for (int d = 0; d < ND; d++) {
                ull g  = add2_(zrow[d], nmuP_s[d * 16 + kg]);
                ull gg = mul2_(g, g);
                acc = fma2(dgP_s[d], gg, acc);
            }
        } else {
            // per-k diag^2 from gmem table (L1-resident 16KB)
            #pragma unroll 4
            for (int d = 0; d < ND; d++) {
                ull dgp = pk2(g_dgKD[kg * ND + d], g_dgKD[(kg + 16) * ND + d]);
                ull g  = add2_(zrow[d], nmuP_s[d * 16 + kg]);
                ull gg = mul2_(g, g);
                acc = fma2(dgp, gg, acc);
            }
        }
        upk2(acc, d2A, d2B);
    } else {
        // full quadratic form fallback: d2 = || Sinv^T (mu - z) ||^2
        const float* zf = reinterpret_cast<const float*>(zrow);
        float d2v[2];
        #pragma unroll
        for (int j = 0; j < 2; j++) {
            int k = kg + j * 16;
            float acc = 0.f;
            for (int e = 0; e < ND; e++) {
                float v = 0.f;
                for (int d = 0; d < ND; d++) {
                    float gd = mu[k * ND + d] - zf[2 * d];
                    v = fmaf(sinv[(k * ND + d) * ND + e], gd, v);
                }
                acc = fmaf(v, v, acc);
            }
            d2v[j] = acc;
        }
        d2A = d2v[0]; d2B = d2v[1];
    }
    d2A = fmaxf(d2A, 0.0f);   // MIN_CLAMP
    d2B = fmaxf(d2B, 0.0f);

    // ---- softmax(-d2) over K, segmented across the 16 lanes of this b ----
    float m = fmaxf(-d2A, -d2B);
    #pragma unroll
    for (int s = 1; s < 16; s <<= 1)
        m = fmaxf(m, __shfl_xor_sync(0xffffffffu, m, s));
    float wA = expf(-d2A - m), wB = expf(-d2B - m);
    float ssum = wA + wB;
    #pragma unroll
    for (int s = 1; s < 16; s <<= 1)
        ssum += __shfl_xor_sync(0xffffffffu, ssum, s);
    float inv = 1.0f / ssum;
    ull w2 = pk2(wA * inv, wB * inv);

    // ---- exogenous drive (packed over cluster pair) ----
    ull ex2 = *reinterpret_cast<const ull*>(&bias_p[kg]);
    #pragma unroll
    for (int e = 0; e < NE; e++) {
        float ue = u_s[bl][e];
        ull bx = *reinterpret_cast<const ull*>(&Bx_p[e][kg]);
        ex2 = fma2(pk2(ue, ue), bx, ex2);
    }

    // ---- AR recurrence: packed pair, circular history ----
    ull a[NORD], h[NORD];
    #pragma unroll
    for (int o = 0; o < NORD; o++) {
        a[o] = *reinterpret_cast<const ull*>(&A_p[o][kg]);
        float yv = yh_s[bl][o];
        h[o] = pk2(yv, yv);
    }

    #pragma unroll
    for (int s = 0; s < NT; s++) {
        ull n = ex2;
        #pragma unroll
        for (int o = 0; o < NORD; o++)
            n = fma2(h[(s + o) & 7], a[o], n);
        h[s & 7] = n;
        ull c = mul2_(w2, n);
        float ca, cb; upk2(c, ca, cb);
        float part = ca + cb;
        part += __shfl_xor_sync(0xffffffffu, part, 8);
        part += __shfl_xor_sync(0xffffffffu, part, 4);
        part += __shfl_xor_sync(0xffffffffu, part, 2);
        if (kg < 2) part2[bl][kg][s] = part;
    }
    __syncthreads();

    // ---- final reduce (2 partials per b) + coalesced float4 store ----
    if (t < TB * NT / 4) {             // 48 threads
        int row = t / (NT / 4);
        int q   = t % (NT / 4);
        float4 p0 = *reinterpret_cast<const float4*>(&part2[row][0][q * 4]);
        float4 p1 = *reinterpret_cast<const float4*>(&part2[row][1][q * 4]);
        float4 v = make_float4(p0.x + p1.x, p0.y + p1.y,
                               p0.z + p1.z, p0.w + p1.w);
        *reinterpret_cast<float4*>(out + (b0 + row) * NT + q * 4) = v;
    }
}

// Safety net: only used if out_size exceeds the expected layout.
__global__ void zero_extra_kernel(float* __restrict__ out, int n0, int n) {
    int i = n0 + blockIdx.x * blockDim.x + threadIdx.x;
    if (i < n) out[i] = 0.0f;
}

extern "C" void kernel_launch(void* const* d_in, const int* in_sizes, int n_in,
                              void* d_out, int out_size) {
    const float* y    = (const float*)d_in[0];
    const float* z    = (const float*)d_in[1];
    const float* u    = (const float*)d_in[2];
    const float* mu   = (const float*)d_in[3];
    const float* sinv = (const float*)d_in[4];
    const float* A    = (const float*)d_in[5];
    const float* Bx   = (const float*)d_in[6];
    const float* bias = (const float*)d_in[7];
    float* out = (float*)d_out;

    prep_kernel<<<NK * 4, THREADS>>>(sinv, mu);
    fused_kernel<<<NB / TB, THREADS>>>(y, z, u, mu, sinv, A, Bx, bias, out);

    int n0 = NB * (NT + NIN);  // fused zeroes [NB*NT, NB*(NT+NIN))
    if (out_size > n0) {
        int extra = out_size - n0;
        zero_extra_kernel<<<(extra + 255) / 256, 256>>>(out, n0, out_size);
    }
}

// round 10
// speedup vs baseline: 1.6951x; 1.0945x over previous
#include <cuda_runtime.h>

#define NB 8192      // batch
#define NK 32        // clusters
#define ND 128       // latent dim
#define NORD 8       // AR order
#define NT 24        // output length
#define NE 16        // exogenous dim
#define NIN 96       // input length
#define TB 8         // batch rows per block
#define THREADS 128  // 16 lanes per b; lane kg owns clusters kg and kg+16
#define NMU_STRIDE 134  // ull row stride: 16B-aligned, conflict-free LDS.128

typedef unsigned long long ull;

// ---- packed fp32x2 helpers (each lane is IEEE fp32; f32x2 via PTX only) ----
__device__ __forceinline__ ull pk2(float lo, float hi) {
    ull r; asm("mov.b64 %0,{%1,%2};" : "=l"(r) : "f"(lo), "f"(hi)); return r;
}
__device__ __forceinline__ void upk2(ull v, float& lo, float& hi) {
    asm("mov.b64 {%0,%1},%2;" : "=f"(lo), "=f"(hi) : "l"(v));
}
__device__ __forceinline__ ull fma2(ull a, ull b, ull c) {
    ull d; asm("fma.rn.f32x2 %0,%1,%2,%3;" : "=l"(d) : "l"(a), "l"(b), "l"(c)); return d;
}
__device__ __forceinline__ ull add2_(ull a, ull b) {
    ull d; asm("add.rn.f32x2 %0,%1,%2;" : "=l"(d) : "l"(a), "l"(b)); return d;
}
__device__ __forceinline__ ull mul2_(ull a, ull b) {
    ull d; asm("mul.rn.f32x2 %0,%1,%2;" : "=l"(d) : "l"(a), "l"(b)); return d;
}

// Scratch (no cudaMalloc). Flags are 0-init at module load and only ever go
// 0 -> 1; all flag states give correct results (set = slower path). Data
// tables are rewritten by prep on every call (deterministic).
__device__ __align__(16) ull   g_nmuP[16 * ND];   // (-mu[kg][d], -mu[kg+16][d]), [kg][d]
__device__ __align__(16) ull   g_dgP [ND];        // (dg0[d], dg0[d]), dg = diag^2
__device__ __align__(16) float g_dgKD[NK * ND];   // diag^2, [k][d] (per-k path)
__device__ int g_general;    // any off-diagonal nonzero -> full quadratic form
__device__ int g_nonuni;     // diag^2 differs across k  -> per-k path
__device__ int g_notscalar;  // diag^2 differs at all    -> per-d path

// grid = 4 blocks per k (128 blocks), 128 threads; float4 scan, MLP=8.
// Blocks 0..15 additionally pack the -mu pair table and dg pair table.
__global__ void prep_kernel(const float* __restrict__ sinv,
                            const float* __restrict__ mu) {
    const int k = blockIdx.x >> 2;
    const int q = blockIdx.x & 3;
    const int t = threadIdx.x;
    const float s00 = sinv[0];
    const float dg00 = s00 * s00;
    const float* S = sinv + k * ND * ND;
    int bad = 0;
    #pragma unroll
    for (int j = 0; j < 8; j++) {
        int i  = j * THREADS + t;       // 0..1023 chunk id within quarter
        int rl = i >> 5, c = i & 31;    // row-local, float4 column
        int row = q * 32 + rl;
        float4 v = *reinterpret_cast<const float4*>(S + row * ND + c * 4);
        int base = c * 4;
        if (base + 0 != row && v.x != 0.0f) bad = 1;
        if (base + 1 != row && v.y != 0.0f) bad = 1;
        if (base + 2 != row && v.z != 0.0f) bad = 1;
        if (base + 3 != row && v.w != 0.0f) bad = 1;
        if (row >= base && row < base + 4) {
            float dv = (row == base) ? v.x : (row == base + 1) ? v.y
                     : (row == base + 2) ? v.z : v.w;
            float dg = dv * dv;
            g_dgKD[k * ND + row] = dg;
            if (dg != dg00) g_notscalar = 1;             // benign race 0->1
            float d0 = sinv[row * ND + row];             // k=0 same-row diag
            if (dg != d0 * d0) g_nonuni = 1;             // benign race 0->1
        }
    }
    if (bad) g_general = 1;                              // benign race 0->1

    // pack tables (first 16 blocks: 16 blocks x 8 d-rows = all 128 d)
    if (blockIdx.x < 16) {
        int d  = blockIdx.x * 8 + (t >> 4);
        int kg = t & 15;
        float mA = mu[kg * ND + d];
        float mB = mu[(kg + 16) * ND + d];
        g_nmuP[kg * ND + d] = pk2(-mA, -mB);
        if (kg == 0) {
            float dv = sinv[d * ND + d];   // k = 0 diagonal
            g_dgP[d] = pk2(dv * dv, dv * dv);
        }
    }
}

__global__ __launch_bounds__(THREADS, 7)
void fused_kernel(const float* __restrict__ y,
                  const float* __restrict__ z,
                  const float* __restrict__ u,
                  const float* __restrict__ mu,
                  const float* __restrict__ sinv,
                  const float* __restrict__ A,
                  const float* __restrict__ Bx,
                  const float* __restrict__ bias,
                  float* __restrict__ out)
{
    // Row stride 134 ull = 1072 B: 16B-aligned rows; bank phase offset
    // 1072/4 mod 32 = 12 -> kg 0..7 start banks {0,12,24,4,16,28,8,20}:
    // LDS.128 conflict-free within each 8-lane phase.
    __shared__ __align__(16) ull   zP[TB][NMU_STRIDE];      // (z,z) pairs
    __shared__ __align__(16) ull   nmuP_s[16][NMU_STRIDE];  // (-muA,-muB)
    __shared__ __align__(16) ull   dgP_s[ND + 2];           // (dg,dg)
    __shared__ __align__(16) float u_s[TB][NE];
    __shared__ __align__(16) float2 A_p[NORD][16];     // (A[kg][o], A[kg+16][o])
    __shared__ __align__(16) float2 Bx_p[NE][16];      // (Bx[kg][e], Bx[kg+16][e])
    __shared__ __align__(16) float2 bias_p[16];
    __shared__ __align__(16) float yh_s[TB][NORD];
    __shared__ __align__(16) float part2[TB][2][28];   // AR partials (2 per b)

    const int t  = threadIdx.x;
    const int b0 = blockIdx.x * TB;
    const int gen   = g_general;
    const int nonu  = g_nonuni;
    const int notsc = g_notscalar;

    // ---- zero this block's x_recon slice (overlaps with staging) ----
    {
        float4 z4 = make_float4(0.f, 0.f, 0.f, 0.f);
        float4* xr = reinterpret_cast<float4*>(out + NB * NT + b0 * NIN);
        xr[t] = z4;                                         // 128 of 192
        if (t < TB * NIN / 4 - THREADS) xr[THREADS + t] = z4;  // last 64
    }

    // ---- cooperative staging ----
    #pragma unroll
    for (int j = 0; j < TB * ND / THREADS; j++) {       // 8 iters
        int i = j * THREADS + t;
        int bl = i >> 7, d = i & 127;
        float zv = z[(b0 + bl) * ND + d];
        zP[bl][d] = pk2(zv, zv);
    }
    {   // nmuP: ull2 copy into strided rows (prep wrote [kg][ND] packed)
        const ulonglong2* src = reinterpret_cast<const ulonglong2*>(g_nmuP);
        #pragma unroll
        for (int j = 0; j < 16 * ND / 2 / THREADS; j++) {  // 8 iters
            int i = j * THREADS + t;
            int kg_ = i >> 6, dq = i & 63;
            *reinterpret_cast<ulonglong2*>(&nmuP_s[kg_][dq * 2]) = src[i];
        }
    }
    dgP_s[t] = g_dgP[t];
    u_s[t >> 4][t & 15] = u[(b0 + (t >> 4)) * NE + (t & 15)];
    {   // A pairs: 128 entries
        int o = t >> 4, kg_ = t & 15;
        A_p[o][kg_] = make_float2(A[kg_ * NORD + o], A[(kg_ + 16) * NORD + o]);
    }
    #pragma unroll
    for (int j = 0; j < 2; j++) {   // Bx pairs: 256 entries
        int i = j * THREADS + t;
        int e = i >> 4, kg_ = i & 15;
        Bx_p[e][kg_] = make_float2(Bx[kg_ * NE + e], Bx[(kg_ + 16) * NE + e]);
    }
    if (t < 16) bias_p[t] = make_float2(bias[t], bias[t + 16]);
    if (t < TB * NORD)
        yh_s[t >> 3][t & 7] = y[(b0 + (t >> 3)) * NIN + (NIN - NORD) + (t & 7)];
    __syncthreads();

    const int bl = t >> 4;    // local batch row (0..7)
    const int kg = t & 15;    // lane within b; clusters kg and kg+16

    // ---- squared Mahalanobis distance, R2/R7 op sequence (frozen):
    //      g = z + (-mu); gg = g*g; acc = fma(dg, gg, acc), d sequential ----
    float d2A, d2B;
    const ull* zrow  = &zP[bl][0];
    const ull* nmrow = &nmuP_s[kg][0];
    if (gen == 0) {
        ull acc = 0ULL;  // packed +0.0f pair (lanes: cluster kg, kg+16)
        if (nonu == 0) {
            if (notsc == 0) {
                // dg is one scalar everywhere: keep it in a register.
                // Bit-identical to fma2(dgP_s[d], ...) since all entries equal.
                const ull dgreg = dgP_s[0];
                #pragma unroll 8
                for (int d = 0; d < ND; d += 2) {
                    ulonglong2 zq = *reinterpret_cast<const ulonglong2*>(&zrow[d]);
                    ulonglong2 nm = *reinterpret_cast<const ulonglong2*>(&nmrow[d]);
                    ull g0 = add2_(zq.x, nm.x);
                    ull g1 = add2_(zq.y, nm.y);
                    acc = fma2(dgreg, mul2_(g0, g0), acc);
                    acc = fma2(dgreg, mul2_(g1, g1), acc);
                }
            } else {
                // per-d dg pairs from smem
                #pragma unroll 4
                for (int d = 0; d < ND; d += 2) {
                    ulonglong2 zq = *reinterpret_cast<const ulonglong2*>(&zrow[d]);
                    ulonglong2 nm = *reinterpret_cast<const ulonglong2*>(&nmrow[d]);
                    ulonglong2 dg = *reinterpret_cast<const ulonglong2*>(&dgP_s[d]);
                    ull g0 = add2_(zq.x, nm.x);
                    ull g1 = add2_(zq.y, nm.y);
                    acc = fma2(dg.x, mul2_(g0, g0), acc);
                    acc = fma2(dg.y, mul2_(g1, g1), acc);
                }
            }
        } else {
            // per-k diag^2 from gmem table (L1-resident 16KB)
            #pragma unroll 4
            for (int d = 0; d < ND; d++) {
                ull dgp = pk2(g_dgKD[kg * ND + d], g_dgKD[(kg + 16) * ND + d]);
                ull g  = add2_(zrow[d], nmrow[d]);
                ull gg = mul2_(g, g);
                acc = fma2(dgp, gg, acc);
            }
        }
        upk2(acc, d2A, d2B);
    } else {
        // full quadratic form fallback: d2 = || Sinv^T (mu - z) ||^2
        const float* zf = reinterpret_cast<const float*>(zrow);
        float d2v[2];
        #pragma unroll
        for (int j = 0; j < 2; j++) {
            int k = kg + j * 16;
            float acc = 0.f;
            for (int e = 0; e < ND; e++) {
                float v = 0.f;
                for (int d = 0; d < ND; d++) {
                    float gd = mu[k * ND + d] - zf[2 * d];
                    v = fmaf(sinv[(k * ND + d) * ND + e], gd, v);
                }
                acc = fmaf(v, v, acc);
            }
            d2v[j] = acc;
        }
        d2A = d2v[0]; d2B = d2v[1];
    }
    d2A = fmaxf(d2A, 0.0f);   // MIN_CLAMP
    d2B = fmaxf(d2B, 0.0f);

    // ---- softmax(-d2) over K, segmented across the 16 lanes of this b ----
    float m = fmaxf(-d2A, -d2B);
    #pragma unroll
    for (int s = 1; s < 16; s <<= 1)
        m = fmaxf(m, __shfl_xor_sync(0xffffffffu, m, s));
    float wA = __expf(-d2A - m), wB = __expf(-d2B - m);
    float ssum = wA + wB;
    #pragma unroll
    for (int s = 1; s < 16; s <<= 1)
        ssum += __shfl_xor_sync(0xffffffffu, ssum, s);
    float inv = 1.0f / ssum;
    ull w2 = pk2(wA * inv, wB * inv);

    // ---- exogenous drive (packed over cluster pair) ----
    ull ex2 = *reinterpret_cast<const ull*>(&bias_p[kg]);
    #pragma unroll
    for (int e = 0; e < NE; e++) {
        float ue = u_s[bl][e];
        ull bx = *reinterpret_cast<const ull*>(&Bx_p[e][kg]);
        ex2 = fma2(pk2(ue, ue), bx, ex2);
    }

    // ---- AR recurrence: packed pair, circular history ----
    ull a[NORD], h[NORD];
    #pragma unroll
    for (int o = 0; o < NORD; o++) {
        a[o] = *reinterpret_cast<const ull*>(&A_p[o][kg]);
        float yv = yh_s[bl][o];
        h[o] = pk2(yv, yv);
    }

    #pragma unroll
    for (int s = 0; s < NT; s++) {
        ull n = ex2;
        #pragma unroll
        for (int o = 0; o < NORD; o++)
            n = fma2(h[(s + o) & 7], a[o], n);
        h[s & 7] = n;
        ull c = mul2_(w2, n);
        float ca, cb; upk2(c, ca, cb);
        float part = ca + cb;
        part += __shfl_xor_sync(0xffffffffu, part, 8);
        part += __shfl_xor_sync(0xffffffffu, part, 4);
        part += __shfl_xor_sync(0xffffffffu, part, 2);
        if (kg < 2) part2[bl][kg][s] = part;
    }
    __syncthreads();

    // ---- final reduce (2 partials per b) + coalesced float4 store ----
    if (t < TB * NT / 4) {             // 48 threads
        int row = t / (NT / 4);
        int q   = t % (NT / 4);
        float4 p0 = *reinterpret_cast<const float4*>(&part2[row][0][q * 4]);
        float4 p1 = *reinterpret_cast<const float4*>(&part2[row][1][q * 4]);
        float4 v = make_float4(p0.x + p1.x, p0.y + p1.y,
                               p0.z + p1.z, p0.w + p1.w);
        *reinterpret_cast<float4*>(out + (b0 + row) * NT + q * 4) = v;
    }
}

// Safety net: only used if out_size exceeds the expected layout.
__global__ void zero_extra_kernel(float* __restrict__ out, int n0, int n) {
    int i = n0 + blockIdx.x * blockDim.x + threadIdx.x;
    if (i < n) out[i] = 0.0f;
}

extern "C" void kernel_launch(void* const* d_in, const int* in_sizes, int n_in,
                              void* d_out, int out_size) {
    const float* y    = (const float*)d_in[0];
    const float* z    = (const float*)d_in[1];
    const float* u    = (const float*)d_in[2];
    const float* mu   = (const float*)d_in[3];
    const float* sinv = (const float*)d_in[4];
    const float* A    = (const float*)d_in[5];
    const float* Bx   = (const float*)d_in[6];
    const float* bias = (const float*)d_in[7];
    float* out = (float*)d_out;

    prep_kernel<<<NK * 4, THREADS>>>(sinv, mu);
    fused_kernel<<<NB / TB, THREADS>>>(y, z, u, mu, sinv, A, Bx, bias, out);

    int n0 = NB * (NT + NIN);  // fused zeroes [NB*NT, NB*(NT+NIN))
    if (out_size > n0) {
        int extra = out_size - n0;
        zero_extra_kernel<<<(extra + 255) / 256, 256>>>(out, n0, out_size);
    }
}

// round 12
// speedup vs baseline: 1.8472x; 1.0897x over previous
#include <cuda_runtime.h>

#define NB 8192      // batch
#define NK 32        // clusters
#define ND 128       // latent dim
#define NORD 8       // AR order
#define NT 24        // output length
#define NE 16        // exogenous dim
#define NIN 96       // input length
#define TB 8         // batch rows per block
#define THREADS 128  // 16 lanes per b; lane kg owns clusters kg and kg+16
#define ZP_STRIDE 130   // ull row stride: 16B-aligned, conflict-free

typedef unsigned long long ull;

// ---- packed fp32x2 helpers (each lane is IEEE fp32; f32x2 via PTX only) ----
__device__ __forceinline__ ull pk2(float lo, float hi) {
    ull r; asm("mov.b64 %0,{%1,%2};" : "=l"(r) : "f"(lo), "f"(hi)); return r;
}
__device__ __forceinline__ void upk2(ull v, float& lo, float& hi) {
    asm("mov.b64 {%0,%1},%2;" : "=f"(lo), "=f"(hi) : "l"(v));
}
__device__ __forceinline__ ull fma2(ull a, ull b, ull c) {
    ull d; asm("fma.rn.f32x2 %0,%1,%2,%3;" : "=l"(d) : "l"(a), "l"(b), "l"(c)); return d;
}
__device__ __forceinline__ ull add2_(ull a, ull b) {
    ull d; asm("add.rn.f32x2 %0,%1,%2;" : "=l"(d) : "l"(a), "l"(b)); return d;
}
__device__ __forceinline__ ull mul2_(ull a, ull b) {
    ull d; asm("mul.rn.f32x2 %0,%1,%2;" : "=l"(d) : "l"(a), "l"(b)); return d;
}

// Scratch (no cudaMalloc). Flags are 0-init at module load and only ever go
// 0 -> 1; all flag states give correct results (set = slower path). Data
// tables are rewritten by prep on every call (deterministic).
// g_nmuT layout [d][16]: each d-row = 16 ull = 128 B = one L1 line.
__device__ __align__(128) ull   g_nmuT[ND * 16];  // (-mu[kg][d], -mu[kg+16][d])
__device__ __align__(16)  ull   g_dgP [ND];       // (dg0[d], dg0[d]), dg = diag^2
__device__ __align__(16)  float g_dgKD[NK * ND];  // diag^2, [k][d] (per-k path)
__device__ int g_general;    // any off-diagonal nonzero -> full quadratic form
__device__ int g_nonuni;     // diag^2 differs across k  -> per-k path
__device__ int g_notscalar;  // diag^2 differs at all    -> per-d path

// grid = 8 blocks per k (256 blocks), 128 threads; float4 scan, MLP=4.
// Blocks 0..15 additionally pack the -mu pair table and dg pair table.
__global__ void prep_kernel(const float* __restrict__ sinv,
                            const float* __restrict__ mu) {
    const int k = blockIdx.x >> 3;
    const int o = blockIdx.x & 7;
    const int t = threadIdx.x;
    const float s00 = sinv[0];
    const float dg00 = s00 * s00;
    const float* S = sinv + k * ND * ND;
    int bad = 0;
    #pragma unroll
    for (int j = 0; j < 4; j++) {
        int i  = j * THREADS + t;       // 0..511 chunk id within octant
        int rl = i >> 5, c = i & 31;    // row-local, float4 column
        int row = o * 16 + rl;
        float4 v = *reinterpret_cast<const float4*>(S + row * ND + c * 4);
        int base = c * 4;
        if (base + 0 != row && v.x != 0.0f) bad = 1;
        if (base + 1 != row && v.y != 0.0f) bad = 1;
        if (base + 2 != row && v.z != 0.0f) bad = 1;
        if (base + 3 != row && v.w != 0.0f) bad = 1;
        if (row >= base && row < base + 4) {
            float dv = (row == base) ? v.x : (row == base + 1) ? v.y
                     : (row == base + 2) ? v.z : v.w;
            float dg = dv * dv;
            g_dgKD[k * ND + row] = dg;
            if (dg != dg00) g_notscalar = 1;             // benign race 0->1
            float d0 = sinv[row * ND + row];             // k=0 same-row diag
            if (dg != d0 * d0) g_nonuni = 1;             // benign race 0->1
        }
    }
    if (bad) g_general = 1;                              // benign race 0->1

    // pack tables (first 16 blocks: 16 blocks x 8 d-rows = all 128 d)
    if (blockIdx.x < 16) {
        int d  = blockIdx.x * 8 + (t >> 4);
        int kg = t & 15;
        float mA = mu[kg * ND + d];
        float mB = mu[(kg + 16) * ND + d];
        g_nmuT[d * 16 + kg] = pk2(-mA, -mB);
        if (kg == 0) {
            float dv = sinv[d * ND + d];   // k = 0 diagonal
            g_dgP[d] = pk2(dv * dv, dv * dv);
        }
    }
}

__global__ __launch_bounds__(THREADS, 8)
void fused_kernel(const float* __restrict__ y,
                  const float* __restrict__ z,
                  const float* __restrict__ u,
                  const float* __restrict__ mu,
                  const float* __restrict__ sinv,
                  const float* __restrict__ A,
                  const float* __restrict__ Bx,
                  const float* __restrict__ bias,
                  float* __restrict__ out)
{
    // zP rows stride 130 ull = 1040 B (16B aligned); two b-rows per warp sit
    // 4 banks apart -> broadcast LDS.128 conflict-free.
    __shared__ __align__(16) ull   zP[TB][ZP_STRIDE];  // (z,z) pairs
    __shared__ __align__(16) ull   dgP_s[ND + 2];      // (dg,dg)
    __shared__ __align__(16) float u_s[TB][NE];
    __shared__ __align__(16) float2 A_p[NORD][16];     // (A[kg][o], A[kg+16][o])
    __shared__ __align__(16) float2 Bx_p[NE][16];      // (Bx[kg][e], Bx[kg+16][e])
    __shared__ __align__(16) float2 bias_p[16];
    __shared__ __align__(16) float yh_s[TB][NORD];
    __shared__ __align__(16) float part2[TB][4][28];   // AR partials (4 per b)

    const int t  = threadIdx.x;
    const int b0 = blockIdx.x * TB;
    const int gen   = g_general;
    const int nonu  = g_nonuni;
    const int notsc = g_notscalar;

    // ---- zero this block's x_recon slice (overlaps with staging) ----
    {
        float4 z4 = make_float4(0.f, 0.f, 0.f, 0.f);
        float4* xr = reinterpret_cast<float4*>(out + NB * NT + b0 * NIN);
        xr[t] = z4;                                         // 128 of 192
        if (t < TB * NIN / 4 - THREADS) xr[THREADS + t] = z4;  // last 64
    }

    // ---- cooperative staging ----
    #pragma unroll
    for (int j = 0; j < TB * ND / THREADS; j++) {       // 8 iters
        int i = j * THREADS + t;
        int bl = i >> 7, d = i & 127;
        float zv = z[(b0 + bl) * ND + d];
        zP[bl][d] = pk2(zv, zv);
    }
    dgP_s[t] = g_dgP[t];
    u_s[t >> 4][t & 15] = u[(b0 + (t >> 4)) * NE + (t & 15)];
    {   // A pairs: 128 entries
        int o = t >> 4, kg_ = t & 15;
        A_p[o][kg_] = make_float2(A[kg_ * NORD + o], A[(kg_ + 16) * NORD + o]);
    }
    #pragma unroll
    for (int j = 0; j < 2; j++) {   // Bx pairs: 256 entries
        int i = j * THREADS + t;
        int e = i >> 4, kg_ = i & 15;
        Bx_p[e][kg_] = make_float2(Bx[kg_ * NE + e], Bx[(kg_ + 16) * NE + e]);
    }
    if (t < 16) bias_p[t] = make_float2(bias[t], bias[t + 16]);
    if (t < TB * NORD)
        yh_s[t >> 3][t & 7] = y[(b0 + (t >> 3)) * NIN + (NIN - NORD) + (t & 7)];
    __syncthreads();

    const int bl = t >> 4;    // local batch row (0..7)
    const int kg = t & 15;    // lane within b; clusters kg and kg+16

    // ---- squared Mahalanobis distance, R2/R7 op sequence (frozen):
    //      g = z + (-mu); gg = g*g; acc = fma(dg, gg, acc), d sequential.
    //      -mu pairs come straight from the L1-resident gmem table. ----
    float d2A, d2B;
    const ull* zrow = &zP[bl][0];
    const ull* nmt  = &g_nmuT[kg];
    if (gen == 0) {
        ull acc = 0ULL;  // packed +0.0f pair (lanes: cluster kg, kg+16)
        if (nonu == 0) {
            if (notsc == 0) {
                // dg is one scalar everywhere: keep it in a register.
                // Bit-identical to fma2(dgP_s[d], ...) since all entries equal.
                const ull dgreg = dgP_s[0];
                #pragma unroll 8
                for (int d = 0; d < ND; d += 2) {
                    ulonglong2 zq = *reinterpret_cast<const ulonglong2*>(&zrow[d]);
                    ull nm0 = nmt[(d + 0) * 16];
                    ull nm1 = nmt[(d + 1) * 16];
                    ull g0 = add2_(zq.x, nm0);
                    ull g1 = add2_(zq.y, nm1);
                    acc = fma2(dgreg, mul2_(g0, g0), acc);
                    acc = fma2(dgreg, mul2_(g1, g1), acc);
                }
            } else {
                // per-d dg pairs from smem
                #pragma unroll 4
                for (int d = 0; d < ND; d += 2) {
                    ulonglong2 zq = *reinterpret_cast<const ulonglong2*>(&zrow[d]);
                    ulonglong2 dg = *reinterpret_cast<const ulonglong2*>(&dgP_s[d]);
                    ull nm0 = nmt[(d + 0) * 16];
                    ull nm1 = nmt[(d + 1) * 16];
                    ull g0 = add2_(zq.x, nm0);
                    ull g1 = add2_(zq.y, nm1);
                    acc = fma2(dg.x, mul2_(g0, g0), acc);
                    acc = fma2(dg.y, mul2_(g1, g1), acc);
                }
            }
        } else {
            // per-k diag^2 from gmem table (L1-resident 16KB)
            #pragma unroll 4
            for (int d = 0; d < ND; d++) {
                ull dgp = pk2(g_dgKD[kg * ND + d], g_dgKD[(kg + 16) * ND + d]);
                ull g  = add2_(zrow[d], nmt[d * 16]);
                ull gg = mul2_(g, g);
                acc = fma2(dgp, gg, acc);
            }
        }
        upk2(acc, d2A, d2B);
    } else {
        // full quadratic form fallback: d2 = || Sinv^T (mu - z) ||^2
        const float* zf = reinterpret_cast<const float*>(zrow);
        float d2v[2];
        #pragma unroll
        for (int j = 0; j < 2; j++) {
            int k = kg + j * 16;
            float acc = 0.f;
            for (int e = 0; e < ND; e++) {
                float v = 0.f;
                for (int d = 0; d < ND; d++) {
                    float gd = mu[k * ND + d] - zf[2 * d];
                    v = fmaf(sinv[(k * ND + d) * ND + e], gd, v);
                }
                acc = fmaf(v, v, acc);
            }
            d2v[j] = acc;
        }
        d2A = d2v[0]; d2B = d2v[1];
    }
    d2A = fmaxf(d2A, 0.0f);   // MIN_CLAMP
    d2B = fmaxf(d2B, 0.0f);

    // ---- softmax(-d2) over K, segmented across the 16 lanes of this b ----
    float m = fmaxf(-d2A, -d2B);
    #pragma unroll
    for (int s = 1; s < 16; s <<= 1)
        m = fmaxf(m, __shfl_xor_sync(0xffffffffu, m, s));
    float wA = __expf(-d2A - m), wB = __expf(-d2B - m);
    float ssum = wA + wB;
    #pragma unroll
    for (int s = 1; s < 16; s <<= 1)
        ssum += __shfl_xor_sync(0xffffffffu, ssum, s);
    float inv = 1.0f / ssum;
    ull w2 = pk2(wA * inv, wB * inv);

    // ---- exogenous drive (packed over cluster pair) ----
    ull ex2 = *reinterpret_cast<const ull*>(&bias_p[kg]);
    #pragma unroll
    for (int e = 0; e < NE; e++) {
        float ue = u_s[bl][e];
        ull bx = *reinterpret_cast<const ull*>(&Bx_p[e][kg]);
        ex2 = fma2(pk2(ue, ue), bx, ex2);
    }

    // ---- AR recurrence: packed pair, circular history ----
    ull a[NORD], h[NORD];
    #pragma unroll
    for (int o = 0; o < NORD; o++) {
        a[o] = *reinterpret_cast<const ull*>(&A_p[o][kg]);
        float yv = yh_s[bl][o];
        h[o] = pk2(yv, yv);
    }

    #pragma unroll
    for (int s = 0; s < NT; s++) {
        ull n = ex2;
        #pragma unroll
        for (int o = 0; o < NORD; o++)
            n = fma2(h[(s + o) & 7], a[o], n);
        h[s & 7] = n;
        ull c = mul2_(w2, n);
        float ca, cb; upk2(c, ca, cb);
        float part = ca + cb;
        part += __shfl_xor_sync(0xffffffffu, part, 8);
        part += __shfl_xor_sync(0xffffffffu, part, 4);
        if (kg < 4) part2[bl][kg][s] = part;
    }
    __syncthreads();

    // ---- final reduce (4 partials per b) + coalesced float4 store ----
    if (t < TB * NT / 4) {             // 48 threads
        int row = t / (NT / 4);
        int q   = t % (NT / 4);
        float4 p0 = *reinterpret_cast<const float4*>(&part2[row][0][q * 4]);
        float4 p1 = *reinterpret_cast<const float4*>(&part2[row][1][q * 4]);
        float4 p2 = *reinterpret_cast<const float4*>(&part2[row][2][q * 4]);
        float4 p3 = *reinterpret_cast<const float4*>(&part2[row][3][q * 4]);
        float4 v = make_float4((p0.x + p1.x) + (p2.x + p3.x),
                               (p0.y + p1.y) + (p2.y + p3.y),
                               (p0.z + p1.z) + (p2.z + p3.z),
                               (p0.w + p1.w) + (p2.w + p3.w));
        *reinterpret_cast<float4*>(out + (b0 + row) * NT + q * 4) = v;
    }
}

// Safety net: only used if out_size exceeds the expected layout.
__global__ void zero_extra_kernel(float* __restrict__ out, int n0, int n) {
    int i = n0 + blockIdx.x * blockDim.x + threadIdx.x;
    if (i < n) out[i] = 0.0f;
}

extern "C" void kernel_launch(void* const* d_in, const int* in_sizes, int n_in,
                              void* d_out, int out_size) {
    const float* y    = (const float*)d_in[0];
    const float* z    = (const float*)d_in[1];
    const float* u    = (const float*)d_in[2];
    const float* mu   = (const float*)d_in[3];
    const float* sinv = (const float*)d_in[4];
    const float* A    = (const float*)d_in[5];
    const float* Bx   = (const float*)d_in[6];
    const float* bias = (const float*)d_in[7];
    float* out = (float*)d_out;

    prep_kernel<<<NK * 8, THREADS>>>(sinv, mu);
    fused_kernel<<<NB / TB, THREADS>>>(y, z, u, mu, sinv, A, Bx, bias, out);

    int n0 = NB * (NT + NIN);  // fused zeroes [NB*NT, NB*(NT+NIN))
    if (out_size > n0) {
        int extra = out_size - n0;
        zero_extra_kernel<<<(extra + 255) / 256, 256>>>(out, n0, out_size);
    }
}

// round 13
// speedup vs baseline: 1.8784x; 1.0169x over previous
#include <cuda_runtime.h>

#define NB 8192      // batch
#define NK 32        // clusters
#define ND 128       // latent dim
#define NORD 8       // AR order
#define NT 24        // output length
#define NE 16        // exogenous dim
#define NIN 96       // input length
#define TB 8         // batch rows per block
#define THREADS 128  // 16 lanes per b; lane kg owns clusters kg and kg+16
#define ZP_STRIDE 130   // ull row stride: 16B-aligned, conflict-free

typedef unsigned long long ull;

// ---- packed fp32x2 helpers (each lane is IEEE fp32; f32x2 via PTX only) ----
__device__ __forceinline__ ull pk2(float lo, float hi) {
    ull r; asm("mov.b64 %0,{%1,%2};" : "=l"(r) : "f"(lo), "f"(hi)); return r;
}
__device__ __forceinline__ void upk2(ull v, float& lo, float& hi) {
    asm("mov.b64 {%0,%1},%2;" : "=f"(lo), "=f"(hi) : "l"(v));
}
__device__ __forceinline__ ull fma2(ull a, ull b, ull c) {
    ull d; asm("fma.rn.f32x2 %0,%1,%2,%3;" : "=l"(d) : "l"(a), "l"(b), "l"(c)); return d;
}
__device__ __forceinline__ ull add2_(ull a, ull b) {
    ull d; asm("add.rn.f32x2 %0,%1,%2;" : "=l"(d) : "l"(a), "l"(b)); return d;
}
__device__ __forceinline__ ull mul2_(ull a, ull b) {
    ull d; asm("mul.rn.f32x2 %0,%1,%2;" : "=l"(d) : "l"(a), "l"(b)); return d;
}

// Scratch (no cudaMalloc). Flags are 0-init at module load and only ever go
// 0 -> 1; all flag states give correct results (set = slower path). Data
// tables are rewritten by prep on every call (deterministic).
// g_nmuT layout [d][16]: each d-row = 16 ull = 128 B = one L1 line.
__device__ __align__(128) ull   g_nmuT[ND * 16];  // (-mu[kg][d], -mu[kg+16][d])
__device__ __align__(16)  ull   g_dgP [ND];       // (dg0[d], dg0[d]), dg = diag^2
__device__ __align__(16)  float g_dgKD[NK * ND];  // diag^2, [k][d] (per-k path)
__device__ int g_general;    // any off-diagonal nonzero -> full quadratic form
__device__ int g_nonuni;     // diag^2 differs across k  -> per-k path
__device__ int g_notscalar;  // diag^2 differs at all    -> per-d path

// grid = 32 blocks per k (1024 blocks), 128 threads; 1 float4 per thread.
// Blocks 0..15 additionally pack the -mu pair table and dg pair table.
__global__ void prep_kernel(const float* __restrict__ sinv,
                            const float* __restrict__ mu) {
    const int k = blockIdx.x >> 5;
    const int q = blockIdx.x & 31;
    const int t = threadIdx.x;
    const float s00 = sinv[0];
    const float dg00 = s00 * s00;
    const float* S = sinv + k * ND * ND;
    int bad = 0;
    {
        int rl = t >> 5, c = t & 31;        // row-local (0..3), float4 column
        int row = q * 4 + rl;
        float4 v = *reinterpret_cast<const float4*>(S + row * ND + c * 4);
        int base = c * 4;
        if (base + 0 != row && v.x != 0.0f) bad = 1;
        if (base + 1 != row && v.y != 0.0f) bad = 1;
        if (base + 2 != row && v.z != 0.0f) bad = 1;
        if (base + 3 != row && v.w != 0.0f) bad = 1;
        if (row >= base && row < base + 4) {
            float dv = (row == base) ? v.x : (row == base + 1) ? v.y
                     : (row == base + 2) ? v.z : v.w;
            float dg = dv * dv;
            g_dgKD[k * ND + row] = dg;
            if (dg != dg00) g_notscalar = 1;             // benign race 0->1
            float d0 = sinv[row * ND + row];             // k=0 same-row diag
            if (dg != d0 * d0) g_nonuni = 1;             // benign race 0->1
        }
    }
    if (bad) g_general = 1;                              // benign race 0->1

    // pack tables (first 16 blocks: 16 blocks x 8 d-rows = all 128 d)
    if (blockIdx.x < 16) {
        int d  = blockIdx.x * 8 + (t >> 4);
        int kg = t & 15;
        float mA = mu[kg * ND + d];
        float mB = mu[(kg + 16) * ND + d];
        g_nmuT[d * 16 + kg] = pk2(-mA, -mB);
        if (kg == 0) {
            float dv = sinv[d * ND + d];   // k = 0 diagonal
            g_dgP[d] = pk2(dv * dv, dv * dv);
        }
    }
}

__global__ __launch_bounds__(THREADS, 8)
void fused_kernel(const float* __restrict__ y,
                  const float* __restrict__ z,
                  const float* __restrict__ u,
                  const float* __restrict__ mu,
                  const float* __restrict__ sinv,
                  const float* __restrict__ A,
                  const float* __restrict__ Bx,
                  const float* __restrict__ bias,
                  float* __restrict__ out)
{
    __shared__ __align__(16) ull   zP[TB][ZP_STRIDE];  // (z,z) pairs
    __shared__ __align__(16) ull   dgP_s[ND + 2];      // (dg,dg)
    __shared__ __align__(16) float u_s[TB][NE];
    __shared__ __align__(16) float2 A_p[NORD][16];     // (A[kg][o], A[kg+16][o])
    __shared__ __align__(16) float2 Bx_p[NE][16];      // (Bx[kg][e], Bx[kg+16][e])
    __shared__ __align__(16) float2 bias_p[16];
    __shared__ __align__(16) float yh_s[TB][NORD];
    __shared__ __align__(16) float rinv_s[TB];         // 1/sum(w) per b
    __shared__ __align__(16) float part2[TB][4][28];   // AR partials (4 per b)

    const int t  = threadIdx.x;
    const int b0 = blockIdx.x * TB;
    const int gen   = g_general;
    const int nonu  = g_nonuni;
    const int notsc = g_notscalar;

    // ---- zero this block's x_recon slice (overlaps with staging) ----
    {
        float4 z4 = make_float4(0.f, 0.f, 0.f, 0.f);
        float4* xr = reinterpret_cast<float4*>(out + NB * NT + b0 * NIN);
        xr[t] = z4;                                         // 128 of 192
        if (t < TB * NIN / 4 - THREADS) xr[THREADS + t] = z4;  // last 64
    }

    // ---- cooperative staging ----
    {   // z via float4: 2 LDG.128 per thread, write (z,z) pairs
        const float4* zsrc = reinterpret_cast<const float4*>(z + b0 * ND);
        #pragma unroll
        for (int j = 0; j < 2; j++) {
            int i4 = j * THREADS + t;          // 0..255
            int row = i4 >> 5, c = i4 & 31;
            float4 v = zsrc[i4];
            ulonglong2 lo; lo.x = pk2(v.x, v.x); lo.y = pk2(v.y, v.y);
            ulonglong2 hi; hi.x = pk2(v.z, v.z); hi.y = pk2(v.w, v.w);
            *reinterpret_cast<ulonglong2*>(&zP[row][c * 4 + 0]) = lo;
            *reinterpret_cast<ulonglong2*>(&zP[row][c * 4 + 2]) = hi;
        }
    }
    dgP_s[t] = g_dgP[t];
    u_s[t >> 4][t & 15] = u[(b0 + (t >> 4)) * NE + (t & 15)];
    {   // A pairs: 128 entries
        int o = t >> 4, kg_ = t & 15;
        A_p[o][kg_] = make_float2(A[kg_ * NORD + o], A[(kg_ + 16) * NORD + o]);
    }
    #pragma unroll
    for (int j = 0; j < 2; j++) {   // Bx pairs: 256 entries
        int i = j * THREADS + t;
        int e = i >> 4, kg_ = i & 15;
        Bx_p[e][kg_] = make_float2(Bx[kg_ * NE + e], Bx[(kg_ + 16) * NE + e]);
    }
    if (t < 16) bias_p[t] = make_float2(bias[t], bias[t + 16]);
    if (t < TB * NORD)
        yh_s[t >> 3][t & 7] = y[(b0 + (t >> 3)) * NIN + (NIN - NORD) + (t & 7)];
    __syncthreads();

    const int bl = t >> 4;    // local batch row (0..7)
    const int kg = t & 15;    // lane within b; clusters kg and kg+16

    // ---- squared Mahalanobis distance, R2/R7 op sequence (frozen):
    //      g = z + (-mu); gg = g*g; acc = fma(dg, gg, acc), d sequential.
    //      -mu pairs come straight from the L1-resident gmem table. ----
    float d2A, d2B;
    const ull* zrow = &zP[bl][0];
    const ull* nmt  = &g_nmuT[kg];
    if (gen == 0) {
        ull acc = 0ULL;  // packed +0.0f pair (lanes: cluster kg, kg+16)
        if (nonu == 0) {
            if (notsc == 0) {
                // dg is one scalar everywhere: keep it in a register.
                // Bit-identical to fma2(dgP_s[d], ...) since all entries equal.
                const ull dgreg = dgP_s[0];
                #pragma unroll 8
                for (int d = 0; d < ND; d += 2) {
                    ulonglong2 zq = *reinterpret_cast<const ulonglong2*>(&zrow[d]);
                    ull nm0 = nmt[(d + 0) * 16];
                    ull nm1 = nmt[(d + 1) * 16];
                    ull g0 = add2_(zq.x, nm0);
                    ull g1 = add2_(zq.y, nm1);
                    acc = fma2(dgreg, mul2_(g0, g0), acc);
                    acc = fma2(dgreg, mul2_(g1, g1), acc);
                }
            } else {
                // per-d dg pairs from smem
                #pragma unroll 4
                for (int d = 0; d < ND; d += 2) {
                    ulonglong2 zq = *reinterpret_cast<const ulonglong2*>(&zrow[d]);
                    ulonglong2 dg = *reinterpret_cast<const ulonglong2*>(&dgP_s[d]);
                    ull nm0 = nmt[(d + 0) * 16];
                    ull nm1 = nmt[(d + 1) * 16];
                    ull g0 = add2_(zq.x, nm0);
                    ull g1 = add2_(zq.y, nm1);
                    acc = fma2(dg.x, mul2_(g0, g0), acc);
                    acc = fma2(dg.y, mul2_(g1, g1), acc);
                }
            }
        } else {
            // per-k diag^2 from gmem table (L1-resident 16KB)
            #pragma unroll 4
            for (int d = 0; d < ND; d++) {
                ull dgp = pk2(g_dgKD[kg * ND + d], g_dgKD[(kg + 16) * ND + d]);
                ull g  = add2_(zrow[d], nmt[d * 16]);
                ull gg = mul2_(g, g);
                acc = fma2(dgp, gg, acc);
            }
        }
        upk2(acc, d2A, d2B);
    } else {
        // full quadratic form fallback: d2 = || Sinv^T (mu - z) ||^2
        const float* zf = reinterpret_cast<const float*>(zrow);
        float d2v[2];
        #pragma unroll
        for (int j = 0; j < 2; j++) {
            int k = kg + j * 16;
            float acc = 0.f;
            for (int e = 0; e < ND; e++) {
                float v = 0.f;
                for (int d = 0; d < ND; d++) {
                    float gd = mu[k * ND + d] - zf[2 * d];
                    v = fmaf(sinv[(k * ND + d) * ND + e], gd, v);
                }
                acc = fmaf(v, v, acc);
            }
            d2v[j] = acc;
        }
        d2A = d2v[0]; d2B = d2v[1];
    }
    d2A = fmaxf(d2A, 0.0f);   // MIN_CLAMP
    d2B = fmaxf(d2B, 0.0f);

    // ---- softmax(-d2), DEFERRED normalization: AR runs on unnormalized w;
    //      the 1/sum(w) scale is applied at the final store. ----
    float m = fmaxf(-d2A, -d2B);
    #pragma unroll
    for (int s = 1; s < 16; s <<= 1)
        m = fmaxf(m, __shfl_xor_sync(0xffffffffu, m, s));
    float wA = __expf(-d2A - m), wB = __expf(-d2B - m);
    ull w2 = pk2(wA, wB);            // unnormalized: AR may start now
    float ssum = wA + wB;            // reduction overlaps AR issue
    #pragma unroll
    for (int s = 1; s < 16; s <<= 1)
        ssum += __shfl_xor_sync(0xffffffffu, ssum, s);
    if (kg == 0) rinv_s[bl] = 1.0f / ssum;

    // ---- exogenous drive (packed over cluster pair) ----
    ull ex2 = *reinterpret_cast<const ull*>(&bias_p[kg]);
    #pragma unroll
    for (int e = 0; e < NE; e++) {
        float ue = u_s[bl][e];
        ull bx = *reinterpret_cast<const ull*>(&Bx_p[e][kg]);
        ex2 = fma2(pk2(ue, ue), bx, ex2);
    }

    // ---- AR recurrence: packed pair, circular history ----
    ull a[NORD], h[NORD];
    #pragma unroll
    for (int o = 0; o < NORD; o++) {
        a[o] = *reinterpret_cast<const ull*>(&A_p[o][kg]);
        float yv = yh_s[bl][o];
        h[o] = pk2(yv, yv);
    }

    #pragma unroll
    for (int s = 0; s < NT; s++) {
        ull n = ex2;
        #pragma unroll
        for (int o = 0; o < NORD; o++)
            n = fma2(h[(s + o) & 7], a[o], n);
        h[s & 7] = n;
        ull c = mul2_(w2, n);
        float ca, cb; upk2(c, ca, cb);
        float part = ca + cb;
        part += __shfl_xor_sync(0xffffffffu, part, 8);
        part += __shfl_xor_sync(0xffffffffu, part, 4);
        if (kg < 4) part2[bl][kg][s] = part;
    }
    __syncthreads();

    // ---- final reduce (4 partials per b), normalize, float4 store ----
    if (t < TB * NT / 4) {             // 48 threads
        int row = t / (NT / 4);
        int q   = t % (NT / 4);
        float rin = rinv_s[row];
        float4 p0 = *reinterpret_cast<const float4*>(&part2[row][0][q * 4]);
        float4 p1 = *reinterpret_cast<const float4*>(&part2[row][1][q * 4]);
        float4 p2 = *reinterpret_cast<const float4*>(&part2[row][2][q * 4]);
        float4 p3 = *reinterpret_cast<const float4*>(&part2[row][3][q * 4]);
        float4 v = make_float4(((p0.x + p1.x) + (p2.x + p3.x)) * rin,
                               ((p0.y + p1.y) + (p2.y + p3.y)) * rin,
                               ((p0.z + p1.z) + (p2.z + p3.z)) * rin,
                               ((p0.w + p1.w) + (p2.w + p3.w)) * rin);
        *reinterpret_cast<float4*>(out + (b0 + row) * NT + q * 4) = v;
    }
}

// Safety net: only used if out_size exceeds the expected layout.
__global__ void zero_extra_kernel(float* __restrict__ out, int n0, int n) {
    int i = n0 + blockIdx.x * blockDim.x + threadIdx.x;
    if (i < n) out[i] = 0.0f;
}

extern "C" void kernel_launch(void* const* d_in, const int* in_sizes, int n_in,
                              void* d_out, int out_size) {
    const float* y    = (const float*)d_in[0];
    const float* z    = (const float*)d_in[1];
    const float* u    = (const float*)d_in[2];
    const float* mu   = (const float*)d_in[3];
    const float* sinv = (const float*)d_in[4];
    const float* A    = (const float*)d_in[5];
    const float* Bx   = (const float*)d_in[6];
    const float* bias = (const float*)d_in[7];
    float* out = (float*)d_out;

    prep_kernel<<<NK * 32, THREADS>>>(sinv, mu);
    fused_kernel<<<NB / TB, THREADS>>>(y, z, u, mu, sinv, A, Bx, bias, out);

    int n0 = NB * (NT + NIN);  // fused zeroes [NB*NT, NB*(NT+NIN))
    if (out_size > n0) {
        int extra = out_size - n0;
        zero_extra_kernel<<<(extra + 255) / 256, 256>>>(out, n0, out_size);
    }
}

// round 15
// speedup vs baseline: 1.8816x; 1.0017x over previous
#include <cuda_runtime.h>

#define NB 8192      // batch
#define NK 32        // clusters
#define ND 128       // latent dim
#define NORD 8       // AR order
#define NT 24        // output length
#define NE 16        // exogenous dim
#define NIN 96       // input length
#define TB 8         // batch rows per block
#define THREADS 128  // 16 lanes per b; lane kg owns clusters kg and kg+16
#define ZP_STRIDE 130   // ull row stride: 16B-aligned, conflict-free

typedef unsigned long long ull;

// ---- packed fp32x2 helpers (each lane is IEEE fp32; f32x2 via PTX only) ----
__device__ __forceinline__ ull pk2(float lo, float hi) {
    ull r; asm("mov.b64 %0,{%1,%2};" : "=l"(r) : "f"(lo), "f"(hi)); return r;
}
__device__ __forceinline__ void upk2(ull v, float& lo, float& hi) {
    asm("mov.b64 {%0,%1},%2;" : "=f"(lo), "=f"(hi) : "l"(v));
}
__device__ __forceinline__ ull fma2(ull a, ull b, ull c) {
    ull d; asm("fma.rn.f32x2 %0,%1,%2,%3;" : "=l"(d) : "l"(a), "l"(b), "l"(c)); return d;
}
__device__ __forceinline__ ull add2_(ull a, ull b) {
    ull d; asm("add.rn.f32x2 %0,%1,%2;" : "=l"(d) : "l"(a), "l"(b)); return d;
}
__device__ __forceinline__ ull mul2_(ull a, ull b) {
    ull d; asm("mul.rn.f32x2 %0,%1,%2;" : "=l"(d) : "l"(a), "l"(b)); return d;
}

// Scratch (no cudaMalloc). Flags are 0-init at module load and only ever go
// 0 -> 1; all flag states give correct results (set = slower path). Data
// tables are rewritten by prep on every call (deterministic).
// g_nmuT2 layout [d/2][kg][2]: lane kg's (d, d+1) operands are 16 contiguous
// bytes -> one LDS.128 after the block copies it to smem.
__device__ __align__(128) ull   g_nmuT2[ND * 16]; // (-mu[kg][d], -mu[kg+16][d])
__device__ __align__(16)  ull   g_dgP [ND];       // (dg0[d], dg0[d]), dg = diag^2
__device__ __align__(16)  float g_dgKD[NK * ND];  // diag^2, [k][d] (per-k path)
__device__ int g_general;    // any off-diagonal nonzero -> full quadratic form
__device__ int g_nonuni;     // diag^2 differs across k  -> per-k path
__device__ int g_notscalar;  // diag^2 differs at all    -> per-d path

// grid = 32 blocks per k (1024 blocks), 128 threads; 1 float4 per thread.
// Blocks 0..15 additionally pack the -mu pair table and dg pair table.
__global__ void prep_kernel(const float* __restrict__ sinv,
                            const float* __restrict__ mu) {
    const int k = blockIdx.x >> 5;
    const int q = blockIdx.x & 31;
    const int t = threadIdx.x;
    const float s00 = sinv[0];
    const float dg00 = s00 * s00;
    const float* S = sinv + k * ND * ND;
    int bad = 0;
    {
        int rl = t >> 5, c = t & 31;        // row-local (0..3), float4 column
        int row = q * 4 + rl;
        float4 v = *reinterpret_cast<const float4*>(S + row * ND + c * 4);
        int base = c * 4;
        if (base + 0 != row && v.x != 0.0f) bad = 1;
        if (base + 1 != row && v.y != 0.0f) bad = 1;
        if (base + 2 != row && v.z != 0.0f) bad = 1;
        if (base + 3 != row && v.w != 0.0f) bad = 1;
        if (row >= base && row < base + 4) {
            float dv = (row == base) ? v.x : (row == base + 1) ? v.y
                     : (row == base + 2) ? v.z : v.w;
            float dg = dv * dv;
            g_dgKD[k * ND + row] = dg;
            if (dg != dg00) g_notscalar = 1;             // benign race 0->1
            float d0 = sinv[row * ND + row];             // k=0 same-row diag
            if (dg != d0 * d0) g_nonuni = 1;             // benign race 0->1
        }
    }
    if (bad) g_general = 1;                              // benign race 0->1

    // pack tables (first 16 blocks: 16 blocks x 8 d-rows = all 128 d)
    if (blockIdx.x < 16) {
        int d  = blockIdx.x * 8 + (t >> 4);
        int kg = t & 15;
        float mA = mu[kg * ND + d];
        float mB = mu[(kg + 16) * ND + d];
        // pair layout: (d,d+1) contiguous per kg
        g_nmuT2[(d >> 1) * 32 + kg * 2 + (d & 1)] = pk2(-mA, -mB);
        if (kg == 0) {
            float dv = sinv[d * ND + d];   // k = 0 diagonal
            g_dgP[d] = pk2(dv * dv, dv * dv);
        }
    }
}

__global__ __launch_bounds__(THREADS, 7)
void fused_kernel(const float* __restrict__ y,
                  const float* __restrict__ z,
                  const float* __restrict__ u,
                  const float* __restrict__ mu,
                  const float* __restrict__ sinv,
                  const float* __restrict__ A,
                  const float* __restrict__ Bx,
                  const float* __restrict__ bias,
                  float* __restrict__ out)
{
    __shared__ __align__(16) ull   nm2_s[ND * 16];     // [d/2][kg][2] pairs, 16KB
    __shared__ __align__(16) ull   zP[TB][ZP_STRIDE];  // (z,z) pairs
    __shared__ __align__(16) float u_s[TB][NE];
    __shared__ __align__(16) float2 A_p[NORD][16];     // (A[kg][o], A[kg+16][o])
    __shared__ __align__(16) float2 Bx_p[NE][16];      // (Bx[kg][e], Bx[kg+16][e])
    __shared__ __align__(16) float2 bias_p[16];
    __shared__ __align__(16) float yh_s[TB][NORD];
    __shared__ __align__(16) float rinv_s[TB];         // 1/sum(w) per b
    __shared__ __align__(16) float part2[TB][4][28];   // AR partials (4 per b)

    const int t  = threadIdx.x;
    const int b0 = blockIdx.x * TB;
    const int gen   = g_general;
    const int nonu  = g_nonuni;
    const int notsc = g_notscalar;

    // ---- zero this block's x_recon slice (overlaps with staging) ----
    {
        float4 z4 = make_float4(0.f, 0.f, 0.f, 0.f);
        float4* xr = reinterpret_cast<float4*>(out + NB * NT + b0 * NIN);
        xr[t] = z4;                                         // 128 of 192
        if (t < TB * NIN / 4 - THREADS) xr[THREADS + t] = z4;  // last 64
    }

    // ---- cooperative staging ----
    {   // nm2 table: straight 16KB copy, 8 x (LDG.128 -> STS.128)
        const ulonglong2* src = reinterpret_cast<const ulonglong2*>(g_nmuT2);
        ulonglong2* dst = reinterpret_cast<ulonglong2*>(nm2_s);
        #pragma unroll
        for (int j = 0; j < ND * 16 / 2 / THREADS; j++)    // 8 iters
            dst[j * THREADS + t] = src[j * THREADS + t];
    }
    {   // z via float4: 2 LDG.128 per thread, write (z,z) pairs
        const float4* zsrc = reinterpret_cast<const float4*>(z + b0 * ND);
        #pragma unroll
        for (int j = 0; j < 2; j++) {
            int i4 = j * THREADS + t;          // 0..255
            int row = i4 >> 5, c = i4 & 31;
            float4 v = zsrc[i4];
            ulonglong2 lo; lo.x = pk2(v.x, v.x); lo.y = pk2(v.y, v.y);
            ulonglong2 hi; hi.x = pk2(v.z, v.z); hi.y = pk2(v.w, v.w);
            *reinterpret_cast<ulonglong2*>(&zP[row][c * 4 + 0]) = lo;
            *reinterpret_cast<ulonglong2*>(&zP[row][c * 4 + 2]) = hi;
        }
    }
    u_s[t >> 4][t & 15] = u[(b0 + (t >> 4)) * NE + (t & 15)];
    {   // A pairs: 128 entries
        int o = t >> 4, kg_ = t & 15;
        A_p[o][kg_] = make_float2(A[kg_ * NORD + o], A[(kg_ + 16) * NORD + o]);
    }
    #pragma unroll
    for (int j = 0; j < 2; j++) {   // Bx pairs: 256 entries
        int i = j * THREADS + t;
        int e = i >> 4, kg_ = i & 15;
        Bx_p[e][kg_] = make_float2(Bx[kg_ * NE + e], Bx[(kg_ + 16) * NE + e]);
    }
    if (t < 16) bias_p[t] = make_float2(bias[t], bias[t + 16]);
    if (t < TB * NORD)
        yh_s[t >> 3][t & 7] = y[(b0 + (t >> 3)) * NIN + (NIN - NORD) + (t & 7)];
    __syncthreads();

    const int bl = t >> 4;    // local batch row (0..7)
    const int kg = t & 15;    // lane within b; clusters kg and kg+16

    // ---- squared Mahalanobis distance, R2/R7 op sequence (frozen):
    //      g = z + (-mu); gg = g*g; acc = fma(dg, gg, acc), d sequential.
    //      Both operand pairs arrive as single LDS.128. ----
    float d2A, d2B;
    const ull* zrow = &zP[bl][0];
    const ull* nmt  = &nm2_s[kg * 2];
    if (gen == 0) {
        ull acc = 0ULL;  // packed +0.0f pair (lanes: cluster kg, kg+16)
        if (nonu == 0) {
            if (notsc == 0) {
                // dg is one scalar everywhere: keep it in a register.
                // Bit-identical to per-element dg since all entries equal.
                const ull dgreg = g_dgP[0];
                #pragma unroll 8
                for (int d = 0; d < ND; d += 2) {
                    ulonglong2 zq = *reinterpret_cast<const ulonglong2*>(&zrow[d]);
                    ulonglong2 nm = *reinterpret_cast<const ulonglong2*>(&nmt[(d >> 1) * 32]);
                    ull g0 = add2_(zq.x, nm.x);
                    ull g1 = add2_(zq.y, nm.y);
                    acc = fma2(dgreg, mul2_(g0, g0), acc);
                    acc = fma2(dgreg, mul2_(g1, g1), acc);
                }
            } else {
                // per-d dg pairs from gmem (L1-resident)
                #pragma unroll 4
                for (int d = 0; d < ND; d += 2) {
                    ulonglong2 zq = *reinterpret_cast<const ulonglong2*>(&zrow[d]);
                    ulonglong2 nm = *reinterpret_cast<const ulonglong2*>(&nmt[(d >> 1) * 32]);
                    ulonglong2 dg = *reinterpret_cast<const ulonglong2*>(&g_dgP[d]);
                    ull g0 = add2_(zq.x, nm.x);
                    ull g1 = add2_(zq.y, nm.y);
                    acc = fma2(dg.x, mul2_(g0, g0), acc);
                    acc = fma2(dg.y, mul2_(g1, g1), acc);
                }
            }
        } else {
            // per-k diag^2 from gmem table (L1-resident 16KB)
            #pragma unroll 4
            for (int d = 0; d < ND; d++) {
                ull dgp = pk2(g_dgKD[kg * ND + d], g_dgKD[(kg + 16) * ND + d]);
                ull g  = add2_(zrow[d], nmt[(d >> 1) * 32 + (d & 1)]);
                ull gg = mul2_(g, g);
                acc = fma2(dgp, gg, acc);
            }
        }
        upk2(acc, d2A, d2B);
    } else {
        // full quadratic form fallback: d2 = || Sinv^T (mu - z) ||^2
        const float* zf = reinterpret_cast<const float*>(zrow);
        float d2v[2];
        #pragma unroll
        for (int j = 0; j < 2; j++) {
            int k = kg + j * 16;
            float acc = 0.f;
            for (int e = 0; e < ND; e++) {
                float v = 0.f;
                for (int d = 0; d < ND; d++) {
                    float gd = mu[k * ND + d] - zf[2 * d];
                    v = fmaf(sinv[(k * ND + d) * ND + e], gd, v);
                }
                acc = fmaf(v, v, acc);
            }
            d2v[j] = acc;
        }
        d2A = d2v[0]; d2B = d2v[1];
    }
    d2A = fmaxf(d2A, 0.0f);   // MIN_CLAMP
    d2B = fmaxf(d2B, 0.0f);

    // ---- softmax(-d2), DEFERRED normalization: AR runs on unnormalized w;
    //      the 1/sum(w) scale is applied at the final store. ----
    float m = fmaxf(-d2A, -d2B);
    #pragma unroll
    for (int s = 1; s < 16; s <<= 1)
        m = fmaxf(m, __shfl_xor_sync(0xffffffffu, m, s));
    float wA = __expf(-d2A - m), wB = __expf(-d2B - m);
    ull w2 = pk2(wA, wB);            // unnormalized: AR may start now
    float ssum = wA + wB;            // reduction overlaps AR issue
    #pragma unroll
    for (int s = 1; s < 16; s <<= 1)
        ssum += __shfl_xor_sync(0xffffffffu, ssum, s);
    if (kg == 0) rinv_s[bl] = 1.0f / ssum;

    // ---- exogenous drive (packed over cluster pair) ----
    ull ex2 = *reinterpret_cast<const ull*>(&bias_p[kg]);
    #pragma unroll
    for (int e = 0; e < NE; e++) {
        float ue = u_s[bl][e];
        ull bx = *reinterpret_cast<const ull*>(&Bx_p[e][kg]);
        ex2 = fma2(pk2(ue, ue), bx, ex2);
    }

    // ---- AR recurrence: packed pair, circular history ----
    ull a[NORD], h[NORD];
    #pragma unroll
    for (int o = 0; o < NORD; o++) {
        a[o] = *reinterpret_cast<const ull*>(&A_p[o][kg]);
        float yv = yh_s[bl][o];
        h[o] = pk2(yv, yv);
    }

    #pragma unroll
    for (int s = 0; s < NT; s++) {
        ull n = ex2;
        #pragma unroll
        for (int o = 0; o < NORD; o++)
            n = fma2(h[(s + o) & 7], a[o], n);
        h[s & 7] = n;
        ull c = mul2_(w2, n);
        float ca, cb; upk2(c, ca, cb);
        float part = ca + cb;
        part += __shfl_xor_sync(0xffffffffu, part, 8);
        part += __shfl_xor_sync(0xffffffffu, part, 4);
        if (kg < 4) part2[bl][kg][s] = part;
    }
    __syncthreads();

    // ---- final reduce (4 partials per b), normalize, float4 store ----
    if (t < TB * NT / 4) {             // 48 threads
        int row = t / (NT / 4);
        int q   = t % (NT / 4);
        float rin = rinv_s[row];
        float4 p0 = *reinterpret_cast<const float4*>(&part2[row][0][q * 4]);
        float4 p1 = *reinterpret_cast<const float4*>(&part2[row][1][q * 4]);
        float4 p2 = *reinterpret_cast<const float4*>(&part2[row][2][q * 4]);
        float4 p3 = *reinterpret_cast<const float4*>(&part2[row][3][q * 4]);
        float4 v = make_float4(((p0.x + p1.x) + (p2.x + p3.x)) * rin,
                               ((p0.y + p1.y) + (p2.y + p3.y)) * rin,
                               ((p0.z + p1.z) + (p2.z + p3.z)) * rin,
                               ((p0.w + p1.w) + (p2.w + p3.w)) * rin);
        *reinterpret_cast<float4*>(out + (b0 + row) * NT + q * 4) = v;
    }
}

// Safety net: only used if out_size exceeds the expected layout.
__global__ void zero_extra_kernel(float* __restrict__ out, int n0, int n) {
    int i = n0 + blockIdx.x * blockDim.x + threadIdx.x;
    if (i < n) out[i] = 0.0f;
}

extern "C" void kernel_launch(void* const* d_in, const int* in_sizes, int n_in,
                              void* d_out, int out_size) {
    const float* y    = (const float*)d_in[0];
    const float* z    = (const float*)d_in[1];
    const float* u    = (const float*)d_in[2];
    const float* mu   = (const float*)d_in[3];
    const float* sinv = (const float*)d_in[4];
    const float* A    = (const float*)d_in[5];
    const float* Bx   = (const float*)d_in[6];
    const float* bias = (const float*)d_in[7];
    float* out = (float*)d_out;

    prep_kernel<<<NK * 32, THREADS>>>(sinv, mu);
    fused_kernel<<<NB / TB, THREADS>>>(y, z, u, mu, sinv, A, Bx, bias, out);

    int n0 = NB * (NT + NIN);  // fused zeroes [NB*NT, NB*(NT+NIN))
    if (out_size > n0) {
        int extra = out_size - n0;
        zero_extra_kernel<<<(extra + 255) / 256, 256>>>(out, n0, out_size);
    }
}